// round 11
// baseline (speedup 1.0000x reference)
#include <cuda_runtime.h>
#include <cuda_bf16.h>
#include <cstdint>

// Problem constants (fixed by setup_inputs)
#define BB 8
#define NN 1024
#define KNN 8
#define MPTS (BB * NN)        // 8192 points
#define MBIG (MPTS * KNN)     // 65536 grouped rows

// ---------------- scratch (static device globals) ---------------------------
__device__ float g_U[MPTS * 1024];
__device__ float g_V[MPTS * 1024];
__device__ float g_Y[MPTS * 1024];     // maxZ / small intermediates
__device__ float g_Z[MPTS * 1024];     // minZ / small intermediates
__device__ __nv_bfloat16 g_aH[MPTS * 1024];
__device__ __nv_bfloat16 g_aL[MPTS * 1024];
__device__ __nv_bfloat16 g_wH[1024 * 1024];
__device__ __nv_bfloat16 g_wL[1024 * 1024];
__device__ int   g_idx[MBIG];
__device__ float g_scale[1024];
__device__ float g_shift[1024];
__device__ float g_ps[1024];
__device__ float g_ps2[1024];

// ======================= helpers =============================================
__device__ __forceinline__ uint32_t smem_u32(const void* p) {
    uint32_t a;
    asm("{ .reg .u64 t; cvta.to.shared.u64 t, %1; cvt.u32.u64 %0, t; }" : "=r"(a) : "l"(p));
    return a;
}
__device__ __forceinline__ void ldsm_x4(uint32_t* r, uint32_t addr) {
    asm volatile("ldmatrix.sync.aligned.m8n8.x4.shared.b16 {%0,%1,%2,%3}, [%4];"
                 : "=r"(r[0]), "=r"(r[1]), "=r"(r[2]), "=r"(r[3]) : "r"(addr));
}
__device__ __forceinline__ void mma16816(float* d, const uint32_t* a, uint32_t b0, uint32_t b1) {
    asm volatile(
        "mma.sync.aligned.m16n8k16.row.col.f32.bf16.bf16.f32 "
        "{%0,%1,%2,%3}, {%4,%5,%6,%7}, {%8,%9}, {%0,%1,%2,%3};"
        : "+f"(d[0]), "+f"(d[1]), "+f"(d[2]), "+f"(d[3])
        : "r"(a[0]), "r"(a[1]), "r"(a[2]), "r"(a[3]), "r"(b0), "r"(b1));
}
__device__ __forceinline__ void split1(float y, __nv_bfloat16& h, __nv_bfloat16& l) {
    h = __float2bfloat16(y);
    l = __float2bfloat16(y - __bfloat162float(h));
}

// ======================= bf16x3 MMA GEMM (UV layers, M=8192) =================
// C[m,n] = sum_k A[m,k]*B[n,k] via AhBh + AlBh + AhBl. 128x128 tile, 8 warps,
// BK=32, 3-stage cp.async. SMEM rows 64B; swizzle chunk c -> c ^ ((row>>1)&3).
__global__ void __launch_bounds__(256) gemm_mma(
    const __nv_bfloat16* __restrict__ Ah, const __nv_bfloat16* __restrict__ Al,
    const __nv_bfloat16* __restrict__ Bh, const __nv_bfloat16* __restrict__ Bl,
    float* __restrict__ C, int M, int K, int Ncol)
{
    __shared__ __align__(16) unsigned char smem[3 * 16384];
    const int tid = threadIdx.x;
    const int wid = tid >> 5, lane = tid & 31;
    const int m0 = blockIdx.y * 128, n0 = blockIdx.x * 128;
    const int warp_m = (wid & 3) * 32;
    const int warp_n = (wid >> 2) * 64;
    const uint32_t sbase = smem_u32(smem);

    float acc[2][8][4];
#pragma unroll
    for (int i = 0; i < 2; i++)
#pragma unroll
        for (int j = 0; j < 8; j++)
#pragma unroll
            for (int q = 0; q < 4; q++) acc[i][j][q] = 0.f;

    const int nch = 3 * (K >> 5);

    auto stage_issue = [&](int g, int s) {
        const __nv_bfloat16* A_;
        const __nv_bfloat16* B_;
        int ka;
        int kk = g * 32;
        if (kk < K)          { A_ = Ah; B_ = Bh; ka = kk; }
        else if (kk < 2 * K) { A_ = Al; B_ = Bh; ka = kk - K; }
        else                 { A_ = Ah; B_ = Bl; ka = kk - 2 * K; }
        int row = tid >> 2;
        int c = tid & 3;
#pragma unroll
        for (int h = 0; h < 2; h++) {
            int r = row + h * 64;
            uint32_t soff = (uint32_t)(s * 16384 + r * 64 + ((c ^ ((r >> 1) & 3)) * 16));
            const void* gp = A_ + (size_t)(m0 + r) * K + ka + c * 8;
            asm volatile("cp.async.cg.shared.global [%0], [%1], 16;" :: "r"(sbase + soff), "l"(gp));
        }
#pragma unroll
        for (int h = 0; h < 2; h++) {
            int r = row + h * 64;
            uint32_t soff = (uint32_t)(s * 16384 + 8192 + r * 64 + ((c ^ ((r >> 1) & 3)) * 16));
            const void* gp = B_ + (size_t)(n0 + r) * K + ka + c * 8;
            asm volatile("cp.async.cg.shared.global [%0], [%1], 16;" :: "r"(sbase + soff), "l"(gp));
        }
        asm volatile("cp.async.commit_group;");
    };

    stage_issue(0, 0);
    if (nch > 1) stage_issue(1, 1);

    for (int g = 0; g < nch; g++) {
        if (g == nch - 1) asm volatile("cp.async.wait_group 0;" ::: "memory");
        else              asm volatile("cp.async.wait_group 1;" ::: "memory");
        __syncthreads();
        if (g + 2 < nch) stage_issue(g + 2, (g + 2) % 3);

        const int s = g % 3;
        const uint32_t sA = sbase + s * 16384;
        const uint32_t sB = sA + 8192;
#pragma unroll
        for (int ks = 0; ks < 2; ks++) {
            uint32_t a[2][4], b[4][4];
#pragma unroll
            for (int mi = 0; mi < 2; mi++) {
                int r = warp_m + mi * 16 + (lane & 15);
                int ch = ks * 2 + (lane >> 4);
                ldsm_x4(a[mi], sA + r * 64 + ((ch ^ ((r >> 1) & 3)) * 16));
            }
#pragma unroll
            for (int nj = 0; nj < 4; nj++) {
                int r = warp_n + nj * 16 + ((lane >> 4) & 1) * 8 + (lane & 7);
                int ch = ks * 2 + ((lane >> 3) & 1);
                ldsm_x4(b[nj], sB + r * 64 + ((ch ^ ((r >> 1) & 3)) * 16));
            }
#pragma unroll
            for (int mi = 0; mi < 2; mi++)
#pragma unroll
                for (int nj = 0; nj < 4; nj++) {
                    mma16816(acc[mi][nj * 2 + 0], a[mi], b[nj][0], b[nj][1]);
                    mma16816(acc[mi][nj * 2 + 1], a[mi], b[nj][2], b[nj][3]);
                }
        }
    }

#pragma unroll
    for (int mi = 0; mi < 2; mi++) {
        int rbase = m0 + warp_m + mi * 16 + (lane >> 2);
#pragma unroll
        for (int ni = 0; ni < 8; ni++) {
            int col = n0 + warp_n + ni * 8 + 2 * (lane & 3);
            *(float2*)&C[(size_t)rbase * Ncol + col] = make_float2(acc[mi][ni][0], acc[mi][ni][1]);
            *(float2*)&C[(size_t)(rbase + 8) * Ncol + col] = make_float2(acc[mi][ni][2], acc[mi][ni][3]);
        }
    }
}

// ======= fused GEMM2: A synthesized from U,V,idx; stats+max in epilogue ======
// A row r = relu(U'[idx[r]] + V'[r>>3])  (U',V' pre-scaled by BN1)
// Outputs: maxZ/minZ (per point, per col) + ps/ps2 (col sums of Z, Z^2).
__global__ void __launch_bounds__(256, 1) gemm_fused2(
    const float* __restrict__ U, const float* __restrict__ V,
    const int* __restrict__ idxN,
    const __nv_bfloat16* __restrict__ BhW, const __nv_bfloat16* __restrict__ BlW,
    float* __restrict__ maxZ, float* __restrict__ minZ,
    float* __restrict__ ps, float* __restrict__ ps2,
    int K, int Ncol)
{
    extern __shared__ __align__(16) unsigned char smem[];   // 3 stages x 32KB
    const int tid = threadIdx.x;
    const int wid = tid >> 5, lane = tid & 31;
    const int m0 = blockIdx.y * 128, n0 = blockIdx.x * 128;
    const int warp_m = (wid & 3) * 32;
    const int warp_n = (wid >> 2) * 64;
    const uint32_t sbase = smem_u32(smem);

    float acc[2][8][4];
#pragma unroll
    for (int i = 0; i < 2; i++)
#pragma unroll
        for (int j = 0; j < 8; j++)
#pragma unroll
            for (int q = 0; q < 4; q++) acc[i][j][q] = 0.f;

    const int nk = K >> 5;

    // A side: thread covers row arow, cols [ahalf*16, ahalf*16+16)
    const int arow = tid >> 1, ahalf = tid & 1;
    const int gr = m0 + arow;
    const int j = idxN[gr];
    const float* Urow = U + ((size_t)((gr >> 13) << 10) + j) * K;
    const float* Vrow = V + (size_t)(gr >> 3) * K;

    float4 u4[4], v4[4];
    auto loadA = [&](int g) {
        const float4* up = (const float4*)(Urow + g * 32 + ahalf * 16);
        const float4* vp = (const float4*)(Vrow + g * 32 + ahalf * 16);
#pragma unroll
        for (int q = 0; q < 4; q++) { u4[q] = up[q]; v4[q] = vp[q]; }
    };
    auto storeA = [&](int s) {
        uint32_t ab = sbase + s * 32768;
        uint32_t x = (arow >> 1) & 3;
        uint32_t hw[8], lw[8];
#pragma unroll
        for (int q = 0; q < 4; q++) {
            const float* uu = (const float*)&u4[q];
            const float* vv = (const float*)&v4[q];
            unsigned short hs[4], ls[4];
#pragma unroll
            for (int e = 0; e < 4; e++) {
                float y = fmaxf(uu[e] + vv[e], 0.f);
                __nv_bfloat16 hb, lb;
                split1(y, hb, lb);
                hs[e] = __bfloat16_as_ushort(hb);
                ls[e] = __bfloat16_as_ushort(lb);
            }
            hw[q * 2]     = (uint32_t)hs[0] | ((uint32_t)hs[1] << 16);
            hw[q * 2 + 1] = (uint32_t)hs[2] | ((uint32_t)hs[3] << 16);
            lw[q * 2]     = (uint32_t)ls[0] | ((uint32_t)ls[1] << 16);
            lw[q * 2 + 1] = (uint32_t)ls[2] | ((uint32_t)ls[3] << 16);
        }
        uint32_t off0 = arow * 64 + (((2 * ahalf)     ^ x) * 16);
        uint32_t off1 = arow * 64 + (((2 * ahalf + 1) ^ x) * 16);
        asm volatile("st.shared.v4.b32 [%0], {%1,%2,%3,%4};" :: "r"(ab + off0), "r"(hw[0]), "r"(hw[1]), "r"(hw[2]), "r"(hw[3]) : "memory");
        asm volatile("st.shared.v4.b32 [%0], {%1,%2,%3,%4};" :: "r"(ab + off1), "r"(hw[4]), "r"(hw[5]), "r"(hw[6]), "r"(hw[7]) : "memory");
        asm volatile("st.shared.v4.b32 [%0], {%1,%2,%3,%4};" :: "r"(ab + 8192 + off0), "r"(lw[0]), "r"(lw[1]), "r"(lw[2]), "r"(lw[3]) : "memory");
        asm volatile("st.shared.v4.b32 [%0], {%1,%2,%3,%4};" :: "r"(ab + 8192 + off1), "r"(lw[4]), "r"(lw[5]), "r"(lw[6]), "r"(lw[7]) : "memory");
    };
    auto issueB = [&](int g, int s) {
        int kc = g * 32;
        uint32_t bb = sbase + s * 32768 + 16384;
        int r = tid >> 1;
        int cb = (tid & 1) * 2;
        uint32_t x = (r >> 1) & 3;
        const __nv_bfloat16* gh = BhW + (size_t)(n0 + r) * K + kc;
        const __nv_bfloat16* gl = BlW + (size_t)(n0 + r) * K + kc;
#pragma unroll
        for (int cc = 0; cc < 2; cc++) {
            uint32_t so = r * 64 + (((cb + cc) ^ x) * 16);
            asm volatile("cp.async.cg.shared.global [%0], [%1], 16;" :: "r"(bb + so), "l"(gh + (cb + cc) * 8));
            asm volatile("cp.async.cg.shared.global [%0], [%1], 16;" :: "r"(bb + 8192 + so), "l"(gl + (cb + cc) * 8));
        }
        asm volatile("cp.async.commit_group;");
    };
    auto mma_chunk = [&](int s) {
        uint32_t aBh = sbase + s * 32768;
        uint32_t aBl = aBh + 8192;
        uint32_t bBh = aBh + 16384;
        uint32_t bBl = aBh + 24576;
#pragma unroll
        for (int ks = 0; ks < 2; ks++) {
            uint32_t ah[2][4], al[2][4], bh[4][4], bl[4][4];
#pragma unroll
            for (int mi = 0; mi < 2; mi++) {
                int r = warp_m + mi * 16 + (lane & 15);
                int ch = ks * 2 + (lane >> 4);
                uint32_t off = r * 64 + ((ch ^ ((r >> 1) & 3)) * 16);
                ldsm_x4(ah[mi], aBh + off);
                ldsm_x4(al[mi], aBl + off);
            }
#pragma unroll
            for (int nj = 0; nj < 4; nj++) {
                int r = warp_n + nj * 16 + ((lane >> 4) & 1) * 8 + (lane & 7);
                int ch = ks * 2 + ((lane >> 3) & 1);
                uint32_t off = r * 64 + ((ch ^ ((r >> 1) & 3)) * 16);
                ldsm_x4(bh[nj], bBh + off);
                ldsm_x4(bl[nj], bBl + off);
            }
#pragma unroll
            for (int mi = 0; mi < 2; mi++)
#pragma unroll
                for (int nj = 0; nj < 4; nj++) {
                    mma16816(acc[mi][nj * 2 + 0], ah[mi], bh[nj][0], bh[nj][1]);
                    mma16816(acc[mi][nj * 2 + 1], ah[mi], bh[nj][2], bh[nj][3]);
                    mma16816(acc[mi][nj * 2 + 0], al[mi], bh[nj][0], bh[nj][1]);
                    mma16816(acc[mi][nj * 2 + 1], al[mi], bh[nj][2], bh[nj][3]);
                    mma16816(acc[mi][nj * 2 + 0], ah[mi], bl[nj][0], bl[nj][1]);
                    mma16816(acc[mi][nj * 2 + 1], ah[mi], bl[nj][2], bl[nj][3]);
                }
        }
    };

    // prologue: stages 0,1 filled; A(2) prefetched into regs
    loadA(0); issueB(0, 0); storeA(0);
    loadA(1); issueB(1, 1); storeA(1);
    if (nk > 2) loadA(2);
    asm volatile("cp.async.wait_group 1;" ::: "memory");
    __syncthreads();

    for (int g = 0; g < nk; g++) {
        mma_chunk(g % 3);
        if (g + 2 < nk) {
            storeA((g + 2) % 3);            // stage freed by the sync entering iter g
            issueB(g + 2, (g + 2) % 3);
        }
        if (g + 3 < nk) loadA(g + 3);
        if (g + 1 < nk) {
            if (g + 2 < nk) asm volatile("cp.async.wait_group 1;" ::: "memory");
            else            asm volatile("cp.async.wait_group 0;" ::: "memory");
            __syncthreads();
        }
    }

    // epilogue: col sums (BN2 stats) + max/min over 8-row groups (k-pool)
    const int col0base = n0 + warp_n;
    const int gbase = (m0 + warp_m) >> 3;
#pragma unroll
    for (int ni = 0; ni < 8; ni++) {
        int col0 = col0base + ni * 8 + 2 * (lane & 3);
        float s0 = 0.f, s1 = 0.f, p0 = 0.f, p1 = 0.f;
#pragma unroll
        for (int mi = 0; mi < 2; mi++)
#pragma unroll
            for (int h = 0; h < 2; h++) {
                float z0 = acc[mi][ni][2 * h], z1 = acc[mi][ni][2 * h + 1];
                s0 += z0; p0 += z0 * z0; s1 += z1; p1 += z1 * z1;
            }
#pragma unroll
        for (int o = 4; o < 32; o <<= 1) {
            s0 += __shfl_xor_sync(0xffffffffu, s0, o);
            s1 += __shfl_xor_sync(0xffffffffu, s1, o);
            p0 += __shfl_xor_sync(0xffffffffu, p0, o);
            p1 += __shfl_xor_sync(0xffffffffu, p1, o);
        }
        if (lane < 4) {
            atomicAdd(&ps[col0], s0);  atomicAdd(&ps[col0 + 1], s1);
            atomicAdd(&ps2[col0], p0); atomicAdd(&ps2[col0 + 1], p1);
        }
#pragma unroll
        for (int mi = 0; mi < 2; mi++)
#pragma unroll
            for (int h = 0; h < 2; h++) {
                float mx0 = acc[mi][ni][2 * h], mx1 = acc[mi][ni][2 * h + 1];
                float mn0 = mx0, mn1 = mx1;
#pragma unroll
                for (int o = 4; o < 32; o <<= 1) {
                    mx0 = fmaxf(mx0, __shfl_xor_sync(0xffffffffu, mx0, o));
                    mx1 = fmaxf(mx1, __shfl_xor_sync(0xffffffffu, mx1, o));
                    mn0 = fminf(mn0, __shfl_xor_sync(0xffffffffu, mn0, o));
                    mn1 = fminf(mn1, __shfl_xor_sync(0xffffffffu, mn1, o));
                }
                if (lane < 4) {
                    int pt = gbase + 2 * mi + h;
                    *(float2*)&maxZ[(size_t)pt * Ncol + col0] = make_float2(mx0, mx1);
                    *(float2*)&minZ[(size_t)pt * Ncol + col0] = make_float2(mn0, mn1);
                }
            }
    }
}

// ======================= fp32 SGEMM (small layers only) ======================
__global__ void sgemm_nt(const float* __restrict__ A, int lda,
                         const float* __restrict__ Bw, int ldb,
                         float* __restrict__ C, int M, int K, int Ncol) {
    __shared__ float As[8][128];
    __shared__ float Bs[8][128];
    const int tid = threadIdx.x;
    const int m0 = blockIdx.y * 128;
    const int n0 = blockIdx.x * 128;
    const int tx = tid % 16;
    const int ty = tid / 16;
    float acc[8][8];
#pragma unroll
    for (int i = 0; i < 8; i++)
#pragma unroll
        for (int j = 0; j < 8; j++) acc[i][j] = 0.f;
    const int lm = tid >> 1;
    const int lk = (tid & 1) * 4;
    for (int k0 = 0; k0 < K; k0 += 8) {
#pragma unroll
        for (int i = 0; i < 4; i++) {
            int kk = lk + i;
            int gm = m0 + lm, gk = k0 + kk;
            float v = 0.f;
            if (gm < M && gk < K) v = A[(long)gm * lda + gk];
            As[kk][lm] = v;
        }
#pragma unroll
        for (int i = 0; i < 4; i++) {
            int kk = lk + i;
            int gn = n0 + lm, gk = k0 + kk;
            float v = 0.f;
            if (gn < Ncol && gk < K) v = Bw[(long)gn * ldb + gk];
            Bs[kk][lm] = v;
        }
        __syncthreads();
#pragma unroll
        for (int kk = 0; kk < 8; kk++) {
            float a[8], b[8];
#pragma unroll
            for (int i = 0; i < 8; i++) a[i] = As[kk][ty * 8 + i];
#pragma unroll
            for (int j = 0; j < 8; j++) b[j] = Bs[kk][tx * 8 + j];
#pragma unroll
            for (int i = 0; i < 8; i++)
#pragma unroll
                for (int j = 0; j < 8; j++) acc[i][j] += a[i] * b[j];
        }
        __syncthreads();
    }
#pragma unroll
    for (int i = 0; i < 8; i++) {
        int gm = m0 + ty * 8 + i;
        if (gm >= M) continue;
#pragma unroll
        for (int j = 0; j < 8; j++) {
            int gn = n0 + tx * 8 + j;
            if (gn < Ncol) C[(long)gm * Ncol + gn] = acc[i][j];
        }
    }
}

// ======================= BN pieces ===========================================
__global__ void zero2(float* a, float* b, int n) {
    int i = blockIdx.x * blockDim.x + threadIdx.x;
    if (i < n) { a[i] = 0.f; b[i] = 0.f; }
}

__global__ void bn_stats_partial(const float* __restrict__ X, int M, int C,
                                 float* __restrict__ psum, float* __restrict__ psum2) {
    int c = blockIdx.x * 32 + threadIdx.x;
    int rows_per = (M + gridDim.y - 1) / gridDim.y;
    int m0 = blockIdx.y * rows_per;
    int m1 = m0 + rows_per; if (m1 > M) m1 = M;
    float s = 0.f, s2 = 0.f;
    for (int m = m0 + threadIdx.y; m < m1; m += 8) {
        float v = X[(long)m * C + c];
        s += v; s2 += v * v;
    }
    __shared__ float sh[8][32], sh2[8][32];
    sh[threadIdx.y][threadIdx.x] = s;
    sh2[threadIdx.y][threadIdx.x] = s2;
    __syncthreads();
    if (threadIdx.y == 0) {
#pragma unroll
        for (int r = 1; r < 8; r++) { s += sh[r][threadIdx.x]; s2 += sh2[r][threadIdx.x]; }
        atomicAdd(&psum[c], s);
        atomicAdd(&psum2[c], s2);
    }
}

// stats over virtual Y[r] = U[idx[r]] + V[r>>3]  (raw, pre-BN)
__global__ void stats_gather(const float* __restrict__ U, const float* __restrict__ V,
                             const int* __restrict__ idxN, int C,
                             float* __restrict__ psum, float* __restrict__ psum2) {
    int c = blockIdx.x * 32 + threadIdx.x;
    int r0 = blockIdx.y * (MBIG / 256);
    float s = 0.f, s2 = 0.f;
    for (int r = r0 + threadIdx.y; r < r0 + (MBIG / 256); r += 8) {
        int j = idxN[r];
        float u = U[((size_t)((r >> 13) << 10) + j) * C + c];
        float v = V[(size_t)(r >> 3) * C + c];
        float y = u + v;
        s += y; s2 += y * y;
    }
    __shared__ float sh[8][32], sh2[8][32];
    sh[threadIdx.y][threadIdx.x] = s;
    sh2[threadIdx.y][threadIdx.x] = s2;
    __syncthreads();
    if (threadIdx.y == 0) {
#pragma unroll
        for (int r = 1; r < 8; r++) { s += sh[r][threadIdx.x]; s2 += sh2[r][threadIdx.x]; }
        atomicAdd(&psum[c], s);
        atomicAdd(&psum2[c], s2);
    }
}

__global__ void bn_finalize(int M, int C,
                            const float* __restrict__ psum, const float* __restrict__ psum2,
                            const float* __restrict__ gamma, const float* __restrict__ beta,
                            float* __restrict__ scale, float* __restrict__ shift) {
    int c = blockIdx.x * blockDim.x + threadIdx.x;
    if (c >= C) return;
    float mean = psum[c] / (float)M;
    float var = psum2[c] / (float)M - mean * mean;
    float sc = gamma[c] * rsqrtf(var + 1e-5f);
    scale[c] = sc;
    shift[c] = beta[c] - mean * sc;
}

__global__ void bn_apply_relu(float* __restrict__ X, long total4, int C4,
                              const float* __restrict__ scale, const float* __restrict__ shift) {
    long i = (long)blockIdx.x * blockDim.x + threadIdx.x;
    if (i >= total4) return;
    int c4 = (int)(i % C4) * 4;
    float4 v = ((float4*)X)[i];
    v.x = fmaxf(v.x * scale[c4 + 0] + shift[c4 + 0], 0.f);
    v.y = fmaxf(v.y * scale[c4 + 1] + shift[c4 + 1], 0.f);
    v.z = fmaxf(v.z * scale[c4 + 2] + shift[c4 + 2], 0.f);
    v.w = fmaxf(v.w * scale[c4 + 3] + shift[c4 + 3], 0.f);
    ((float4*)X)[i] = v;
}

// apply BN+relu, write bf16 hi/lo splits
__global__ void bn_apply_split(const float* __restrict__ X, long total4, int C4,
                               const float* __restrict__ scale, const float* __restrict__ shift,
                               __nv_bfloat16* __restrict__ H, __nv_bfloat16* __restrict__ L) {
    long i = (long)blockIdx.x * blockDim.x + threadIdx.x;
    if (i >= total4) return;
    int c4 = (int)(i % C4) * 4;
    float4 v = ((const float4*)X)[i];
    float y0 = fmaxf(v.x * scale[c4 + 0] + shift[c4 + 0], 0.f);
    float y1 = fmaxf(v.y * scale[c4 + 1] + shift[c4 + 1], 0.f);
    float y2 = fmaxf(v.z * scale[c4 + 2] + shift[c4 + 2], 0.f);
    float y3 = fmaxf(v.w * scale[c4 + 3] + shift[c4 + 3], 0.f);
    __nv_bfloat16 h0, l0, h1, l1, h2, l2, h3, l3;
    split1(y0, h0, l0); split1(y1, h1, l1); split1(y2, h2, l2); split1(y3, h3, l3);
    __nv_bfloat162* H2 = (__nv_bfloat162*)H;
    __nv_bfloat162* L2 = (__nv_bfloat162*)L;
    H2[2 * i] = __nv_bfloat162(h0, h1); H2[2 * i + 1] = __nv_bfloat162(h2, h3);
    L2[2 * i] = __nv_bfloat162(l0, l1); L2[2 * i + 1] = __nv_bfloat162(l2, l3);
}

// in-place pre-scale: U *= s[c];  V = V*s[c] + t[c]
__global__ void scale_uv(float* __restrict__ U, float* __restrict__ V,
                         const float* __restrict__ sc, const float* __restrict__ sh, int C) {
    long total4 = (long)MPTS * C / 4;
    long i = (long)blockIdx.x * blockDim.x + threadIdx.x;
    if (i >= total4) return;
    int c4 = (int)(i % (C / 4)) * 4;
    float4 u = ((float4*)U)[i];
    float4 v = ((float4*)V)[i];
    u.x *= sc[c4 + 0]; u.y *= sc[c4 + 1]; u.z *= sc[c4 + 2]; u.w *= sc[c4 + 3];
    v.x = fmaf(v.x, sc[c4 + 0], sh[c4 + 0]);
    v.y = fmaf(v.y, sc[c4 + 1], sh[c4 + 1]);
    v.z = fmaf(v.z, sc[c4 + 2], sh[c4 + 2]);
    v.w = fmaf(v.w, sc[c4 + 3], sh[c4 + 3]);
    ((float4*)U)[i] = u;
    ((float4*)V)[i] = v;
}

// out = relu(affine(max/min)) -> bf16 splits (local_op A output)
__global__ void bn_pick_split(const float* __restrict__ maxZ, const float* __restrict__ minZ, int C,
                              const float* __restrict__ scale, const float* __restrict__ shift,
                              __nv_bfloat16* __restrict__ H, __nv_bfloat16* __restrict__ L) {
    long total = (long)MPTS * C;
    long i = (long)blockIdx.x * blockDim.x + threadIdx.x;
    if (i >= total) return;
    int c = (int)(i % C);
    float s = scale[c];
    float z = (s >= 0.f) ? maxZ[i] : minZ[i];
    float y = fmaxf(fmaf(z, s, shift[c]), 0.f);
    __nv_bfloat16 h, l; split1(y, h, l);
    H[i] = h; L[i] = l;
}

// final: relu(affine(max/min)) + transpose -> out (B, C, N)
__global__ void bn_pick_tr(const float* __restrict__ maxZ, const float* __restrict__ minZ,
                           float* __restrict__ out, int C,
                           const float* __restrict__ scale, const float* __restrict__ shift) {
    __shared__ float t[32][33];
    int c = blockIdx.x * 32 + threadIdx.x;
    int n = blockIdx.y * 32 + threadIdx.y;
    int b = blockIdx.z;
    size_t i = (size_t)(b * NN + n) * C + c;
    float s = scale[c];
    float z = (s >= 0.f) ? maxZ[i] : minZ[i];
    t[threadIdx.y][threadIdx.x] = fmaxf(fmaf(z, s, shift[c]), 0.f);
    __syncthreads();
    out[((size_t)b * C + blockIdx.x * 32 + threadIdx.y) * NN + blockIdx.y * 32 + threadIdx.x] =
        t[threadIdx.x][threadIdx.y];
}

// ======================= weight splits =======================================
__global__ void wsplit(const float* __restrict__ W, int rows, int cols, int ld, int coloff,
                       __nv_bfloat16* __restrict__ H, __nv_bfloat16* __restrict__ L) {
    long total = (long)rows * cols;
    long i = (long)blockIdx.x * blockDim.x + threadIdx.x;
    if (i >= total) return;
    int r = (int)(i / cols), c = (int)(i % cols);
    float x = W[(long)r * ld + coloff + c];
    __nv_bfloat16 h, l; split1(x, h, l);
    H[i] = h; L[i] = l;
}

__global__ void wdiff_split(const float* __restrict__ W, int O, int Ck,
                            __nv_bfloat16* __restrict__ H, __nv_bfloat16* __restrict__ L) {
    long total = (long)O * Ck;
    long i = (long)blockIdx.x * blockDim.x + threadIdx.x;
    if (i >= total) return;
    int o = (int)(i / Ck), d = (int)(i % Ck);
    float x = W[(long)o * 2 * Ck + Ck + d] - W[(long)o * 2 * Ck + d];
    __nv_bfloat16 h, l; split1(x, h, l);
    H[i] = h; L[i] = l;
}

// ======================= kNN (k=8 incl. self) ================================
__global__ void knn_kernel(const float* __restrict__ xyz, int* __restrict__ idx) {
    int b = blockIdx.x;
    __shared__ float sx[NN], sy[NN], sz[NN];
    const float* base = xyz + (long)b * NN * 3;
    for (int i = threadIdx.x; i < NN; i += blockDim.x) {
        sx[i] = base[i * 3 + 0];
        sy[i] = base[i * 3 + 1];
        sz[i] = base[i * 3 + 2];
    }
    __syncthreads();
    int q = blockIdx.y * 256 + threadIdx.x;
    float qx = sx[q], qy = sy[q], qz = sz[q];
    float bd[KNN]; int bi[KNN];
#pragma unroll
    for (int t = 0; t < KNN; t++) { bd[t] = 3.0e38f; bi[t] = 0; }
    for (int jj = 0; jj < NN; jj++) {
        float dx = sx[jj] - qx, dy = sy[jj] - qy, dz = sz[jj] - qz;
        float d = dx * dx + dy * dy + dz * dz;
        if (d < bd[KNN - 1]) {
            int p = KNN - 1;
#pragma unroll
            for (int t = 0; t < KNN - 1; t++) {
                if (p > 0 && d < bd[p - 1]) { bd[p] = bd[p - 1]; bi[p] = bi[p - 1]; p--; }
            }
            bd[p] = d; bi[p] = jj;
        }
    }
#pragma unroll
    for (int t = 0; t < KNN; t++) idx[(b * NN + q) * KNN + t] = bi[t];
}

// ======================= host orchestration ==================================
extern "C" void kernel_launch(void* const* d_in, const int* in_sizes, int n_in,
                              void* d_out, int out_size) {
    const float* xyz = (const float*)d_in[0];
    const float* W1  = (const float*)d_in[1];
    const float* g1  = (const float*)d_in[2];
    const float* b1  = (const float*)d_in[3];
    const float* W2  = (const float*)d_in[4];
    const float* g2  = (const float*)d_in[5];
    const float* b2  = (const float*)d_in[6];
    const float* WA1 = (const float*)d_in[7];
    const float* gA1 = (const float*)d_in[8];
    const float* bA1 = (const float*)d_in[9];
    const float* WA2 = (const float*)d_in[10];
    const float* gA2 = (const float*)d_in[11];
    const float* bA2 = (const float*)d_in[12];
    const float* WB1 = (const float*)d_in[13];
    const float* gB1 = (const float*)d_in[14];
    const float* bB1 = (const float*)d_in[15];
    const float* WB2 = (const float*)d_in[16];
    const float* gB2 = (const float*)d_in[17];
    const float* bB2 = (const float*)d_in[18];
    float* out = (float*)d_out;

    float *U, *V, *Y, *Z, *scale, *shift, *ps, *ps2;
    __nv_bfloat16 *aH, *aL, *wH, *wL;
    int* idx;
    cudaGetSymbolAddress((void**)&U, g_U);
    cudaGetSymbolAddress((void**)&V, g_V);
    cudaGetSymbolAddress((void**)&Y, g_Y);
    cudaGetSymbolAddress((void**)&Z, g_Z);
    cudaGetSymbolAddress((void**)&aH, g_aH);
    cudaGetSymbolAddress((void**)&aL, g_aL);
    cudaGetSymbolAddress((void**)&wH, g_wH);
    cudaGetSymbolAddress((void**)&wL, g_wL);
    cudaGetSymbolAddress((void**)&idx, g_idx);
    cudaGetSymbolAddress((void**)&scale, g_scale);
    cudaGetSymbolAddress((void**)&shift, g_shift);
    cudaGetSymbolAddress((void**)&ps, g_ps);
    cudaGetSymbolAddress((void**)&ps2, g_ps2);

    cudaFuncSetAttribute(gemm_fused2, cudaFuncAttributeMaxDynamicSharedMemorySize, 3 * 32768);

    auto gemm32 = [&](const float* A, int lda, const float* Bw, int ldb,
                      float* Cm, int M, int K, int Nc) {
        dim3 gs((Nc + 127) / 128, (M + 127) / 128);
        sgemm_nt<<<gs, 256>>>(A, lda, Bw, ldb, Cm, M, K, Nc);
    };
    auto gemmtc = [&](const __nv_bfloat16* Ahh, const __nv_bfloat16* All,
                      const __nv_bfloat16* Bhh, const __nv_bfloat16* Bll,
                      float* Cm, int M, int K, int Nc) {
        dim3 gs(Nc / 128, M / 128);
        gemm_mma<<<gs, 256>>>(Ahh, All, Bhh, Bll, Cm, M, K, Nc);
    };
    auto stats = [&](const float* X, int M, int C, const float* gm, const float* bt) {
        zero2<<<(C + 255) / 256, 256>>>(ps, ps2, C);
        dim3 bs(32, 8), gs(C / 32, 32);
        bn_stats_partial<<<gs, bs>>>(X, M, C, ps, ps2);
        bn_finalize<<<(C + 255) / 256, 256>>>(M, C, ps, ps2, gm, bt, scale, shift);
    };

    // Layer 1: (8192,3)@W1^T -> Y(:,64); BN+relu fp32 in place
    gemm32(xyz, 3, W1, 3, Y, MPTS, 3, 64);
    stats(Y, MPTS, 64, g1, b1);
    {
        long t4 = (long)MPTS * 64 / 4;
        bn_apply_relu<<<(unsigned)((t4 + 255) / 256), 256>>>(Y, t4, 16, scale, shift);
    }
    // Layer 2: h1@W2^T -> Z(:,256); BN+relu -> bf16 splits (h2 feat)
    gemm32(Y, 64, W2, 64, Z, MPTS, 64, 256);
    stats(Z, MPTS, 256, g2, b2);
    {
        long t4 = (long)MPTS * 256 / 4;
        bn_apply_split<<<(unsigned)((t4 + 255) / 256), 256>>>(Z, t4, 64, scale, shift, aH, aL);
    }

    // kNN indices
    {
        dim3 gs(BB, 4);
        knn_kernel<<<gs, 256>>>(xyz, idx);
    }

    auto local_op = [&](int Cin, int C2, const float* Wm1, const float* gm1, const float* bt1,
                        const float* Wm2, const float* gm2, const float* bt2, bool last) {
        // U = feat@Wd^T ; V = feat@(Wc-Wd)^T   (feat = aH/aL splits, 8192 x Cin)
        wsplit<<<((long)C2 * Cin + 255) / 256, 256>>>(Wm1, C2, Cin, 2 * Cin, 0, wH, wL);
        gemmtc(aH, aL, wH, wL, U, MPTS, Cin, C2);
        wdiff_split<<<((long)C2 * Cin + 255) / 256, 256>>>(Wm1, C2, Cin, wH, wL);
        gemmtc(aH, aL, wH, wL, V, MPTS, Cin, C2);
        // BN1 stats over virtual Y, then pre-scale U,V in place
        zero2<<<(C2 + 255) / 256, 256>>>(ps, ps2, C2);
        {
            dim3 bs(32, 8), gs(C2 / 32, 256);
            stats_gather<<<gs, bs>>>(U, V, idx, C2, ps, ps2);
        }
        bn_finalize<<<(C2 + 255) / 256, 256>>>(MBIG, C2, ps, ps2, gm1, bt1, scale, shift);
        {
            long t4 = (long)MPTS * C2 / 4;
            scale_uv<<<(unsigned)((t4 + 255) / 256), 256>>>(U, V, scale, shift, C2);
        }
        // fused GEMM2 (M=65536) with stats + k-max epilogue
        wsplit<<<((long)C2 * C2 + 255) / 256, 256>>>(Wm2, C2, C2, C2, 0, wH, wL);
        zero2<<<(C2 + 255) / 256, 256>>>(ps, ps2, C2);
        {
            dim3 gs(C2 / 128, MBIG / 128);
            gemm_fused2<<<gs, 256, 3 * 32768>>>(U, V, idx, wH, wL, Y, Z, ps, ps2, C2, C2);
        }
        bn_finalize<<<(C2 + 255) / 256, 256>>>(MBIG, C2, ps, ps2, gm2, bt2, scale, shift);
        if (!last) {
            long t = (long)MPTS * C2;
            bn_pick_split<<<(unsigned)((t + 255) / 256), 256>>>(Y, Z, C2, scale, shift, aH, aL);
        } else {
            dim3 bs(32, 32), gs(C2 / 32, NN / 32, BB);
            bn_pick_tr<<<gs, bs>>>(Y, Z, out, C2, scale, shift);
        }
    };

    local_op(256, 512, WA1, gA1, bA1, WA2, gA2, bA2, false);
    local_op(512, 1024, WB1, gB1, bB1, WB2, gB2, bB2, true);
}

// round 13
// speedup vs baseline: 1.1302x; 1.1302x over previous
#include <cuda_runtime.h>
#include <cuda_bf16.h>
#include <cstdint>

#define BB 8
#define NN 1024
#define KNN 8
#define MPTS (BB * NN)        // 8192 points
#define MBIG (MPTS * KNN)     // 65536 grouped rows

// ---------------- scratch (static device globals) ---------------------------
__device__ float g_U[MPTS * 1024];
__device__ float g_V[MPTS * 1024];
__device__ float g_Y[MPTS * 1024];     // maxZ
__device__ float g_Z[MPTS * 1024];     // minZ
__device__ __nv_bfloat16 g_aH[(size_t)MBIG * 1024];
__device__ __nv_bfloat16 g_aL[(size_t)MBIG * 1024];
__device__ __nv_bfloat16 g_wH[1024 * 1024];
__device__ __nv_bfloat16 g_wL[1024 * 1024];
__device__ int   g_idx[MBIG];
__device__ float g_scale[1024];
__device__ float g_shift[1024];
__device__ float g_ps[1024];
__device__ float g_ps2[1024];

// ======================= helpers =============================================
__device__ __forceinline__ uint32_t smem_u32(const void* p) {
    uint32_t a;
    asm("{ .reg .u64 t; cvta.to.shared.u64 t, %1; cvt.u32.u64 %0, t; }" : "=r"(a) : "l"(p));
    return a;
}
__device__ __forceinline__ void ldsm_x4(uint32_t* r, uint32_t addr) {
    asm volatile("ldmatrix.sync.aligned.m8n8.x4.shared.b16 {%0,%1,%2,%3}, [%4];"
                 : "=r"(r[0]), "=r"(r[1]), "=r"(r[2]), "=r"(r[3]) : "r"(addr));
}
__device__ __forceinline__ void mma16816(float* d, const uint32_t* a, uint32_t b0, uint32_t b1) {
    asm volatile(
        "mma.sync.aligned.m16n8k16.row.col.f32.bf16.bf16.f32 "
        "{%0,%1,%2,%3}, {%4,%5,%6,%7}, {%8,%9}, {%0,%1,%2,%3};"
        : "+f"(d[0]), "+f"(d[1]), "+f"(d[2]), "+f"(d[3])
        : "r"(a[0]), "r"(a[1]), "r"(a[2]), "r"(a[3]), "r"(b0), "r"(b1));
}
__device__ __forceinline__ void split1(float y, __nv_bfloat16& h, __nv_bfloat16& l) {
    h = __float2bfloat16(y);
    l = __float2bfloat16(y - __bfloat162float(h));
}

// ======================= bf16x3 MMA GEMM (writes C) ==========================
// C[m,n] = sum_k A[m,k]*B[n,k] via AhBh + AlBh + AhBl. 128x128 tile, 8 warps,
// BK=32, 3-stage cp.async, 48KB static smem (2 CTA/SM).
__global__ void __launch_bounds__(256) gemm_mma(
    const __nv_bfloat16* __restrict__ Ah, const __nv_bfloat16* __restrict__ Al,
    const __nv_bfloat16* __restrict__ Bh, const __nv_bfloat16* __restrict__ Bl,
    float* __restrict__ C, int M, int K, int Ncol)
{
    __shared__ __align__(16) unsigned char smem[3 * 16384];
    const int tid = threadIdx.x;
    const int wid = tid >> 5, lane = tid & 31;
    const int m0 = blockIdx.y * 128, n0 = blockIdx.x * 128;
    const int warp_m = (wid & 3) * 32;
    const int warp_n = (wid >> 2) * 64;
    const uint32_t sbase = smem_u32(smem);

    float acc[2][8][4];
#pragma unroll
    for (int i = 0; i < 2; i++)
#pragma unroll
        for (int j = 0; j < 8; j++)
#pragma unroll
            for (int q = 0; q < 4; q++) acc[i][j][q] = 0.f;

    const int nch = 3 * (K >> 5);

    auto stage_issue = [&](int g, int s) {
        const __nv_bfloat16* A_;
        const __nv_bfloat16* B_;
        int ka;
        int kk = g * 32;
        if (kk < K)          { A_ = Ah; B_ = Bh; ka = kk; }
        else if (kk < 2 * K) { A_ = Al; B_ = Bh; ka = kk - K; }
        else                 { A_ = Ah; B_ = Bl; ka = kk - 2 * K; }
        int row = tid >> 2;
        int c = tid & 3;
#pragma unroll
        for (int h = 0; h < 2; h++) {
            int r = row + h * 64;
            uint32_t soff = (uint32_t)(s * 16384 + r * 64 + ((c ^ ((r >> 1) & 3)) * 16));
            const void* gp = A_ + (size_t)(m0 + r) * K + ka + c * 8;
            asm volatile("cp.async.cg.shared.global [%0], [%1], 16;" :: "r"(sbase + soff), "l"(gp));
        }
#pragma unroll
        for (int h = 0; h < 2; h++) {
            int r = row + h * 64;
            uint32_t soff = (uint32_t)(s * 16384 + 8192 + r * 64 + ((c ^ ((r >> 1) & 3)) * 16));
            const void* gp = B_ + (size_t)(n0 + r) * K + ka + c * 8;
            asm volatile("cp.async.cg.shared.global [%0], [%1], 16;" :: "r"(sbase + soff), "l"(gp));
        }
        asm volatile("cp.async.commit_group;");
    };

    stage_issue(0, 0);
    if (nch > 1) stage_issue(1, 1);

    for (int g = 0; g < nch; g++) {
        if (g == nch - 1) asm volatile("cp.async.wait_group 0;" ::: "memory");
        else              asm volatile("cp.async.wait_group 1;" ::: "memory");
        __syncthreads();
        if (g + 2 < nch) stage_issue(g + 2, (g + 2) % 3);

        const int s = g % 3;
        const uint32_t sA = sbase + s * 16384;
        const uint32_t sB = sA + 8192;
#pragma unroll
        for (int ks = 0; ks < 2; ks++) {
            uint32_t a[2][4], b[4][4];
#pragma unroll
            for (int mi = 0; mi < 2; mi++) {
                int r = warp_m + mi * 16 + (lane & 15);
                int ch = ks * 2 + (lane >> 4);
                ldsm_x4(a[mi], sA + r * 64 + ((ch ^ ((r >> 1) & 3)) * 16));
            }
#pragma unroll
            for (int nj = 0; nj < 4; nj++) {
                int r = warp_n + nj * 16 + ((lane >> 4) & 1) * 8 + (lane & 7);
                int ch = ks * 2 + ((lane >> 3) & 1);
                ldsm_x4(b[nj], sB + r * 64 + ((ch ^ ((r >> 1) & 3)) * 16));
            }
#pragma unroll
            for (int mi = 0; mi < 2; mi++)
#pragma unroll
                for (int nj = 0; nj < 4; nj++) {
                    mma16816(acc[mi][nj * 2 + 0], a[mi], b[nj][0], b[nj][1]);
                    mma16816(acc[mi][nj * 2 + 1], a[mi], b[nj][2], b[nj][3]);
                }
        }
    }

#pragma unroll
    for (int mi = 0; mi < 2; mi++) {
        int rbase = m0 + warp_m + mi * 16 + (lane >> 2);
#pragma unroll
        for (int ni = 0; ni < 8; ni++) {
            int col = n0 + warp_n + ni * 8 + 2 * (lane & 3);
            *(float2*)&C[(size_t)rbase * Ncol + col] = make_float2(acc[mi][ni][0], acc[mi][ni][1]);
            *(float2*)&C[(size_t)(rbase + 8) * Ncol + col] = make_float2(acc[mi][ni][2], acc[mi][ni][3]);
        }
    }
}

// ====== gemm_pool: SAME mainloop as gemm_mma; epilogue = stats + k-pool ======
// M = MBIG. Instead of writing C, accumulates ps/ps2 (col sums of Z, Z^2) and
// writes maxZ/minZ per point (max/min over the 8 consecutive k-rows).
__global__ void __launch_bounds__(256) gemm_pool(
    const __nv_bfloat16* __restrict__ Ah, const __nv_bfloat16* __restrict__ Al,
    const __nv_bfloat16* __restrict__ Bh, const __nv_bfloat16* __restrict__ Bl,
    float* __restrict__ maxZ, float* __restrict__ minZ,
    float* __restrict__ ps, float* __restrict__ ps2,
    int K, int Ncol)
{
    __shared__ __align__(16) unsigned char smem[3 * 16384];
    const int tid = threadIdx.x;
    const int wid = tid >> 5, lane = tid & 31;
    const int m0 = blockIdx.y * 128, n0 = blockIdx.x * 128;
    const int warp_m = (wid & 3) * 32;
    const int warp_n = (wid >> 2) * 64;
    const uint32_t sbase = smem_u32(smem);

    float acc[2][8][4];
#pragma unroll
    for (int i = 0; i < 2; i++)
#pragma unroll
        for (int j = 0; j < 8; j++)
#pragma unroll
            for (int q = 0; q < 4; q++) acc[i][j][q] = 0.f;

    const int nch = 3 * (K >> 5);

    auto stage_issue = [&](int g, int s) {
        const __nv_bfloat16* A_;
        const __nv_bfloat16* B_;
        int ka;
        int kk = g * 32;
        if (kk < K)          { A_ = Ah; B_ = Bh; ka = kk; }
        else if (kk < 2 * K) { A_ = Al; B_ = Bh; ka = kk - K; }
        else                 { A_ = Ah; B_ = Bl; ka = kk - 2 * K; }
        int row = tid >> 2;
        int c = tid & 3;
#pragma unroll
        for (int h = 0; h < 2; h++) {
            int r = row + h * 64;
            uint32_t soff = (uint32_t)(s * 16384 + r * 64 + ((c ^ ((r >> 1) & 3)) * 16));
            const void* gp = A_ + (size_t)(m0 + r) * K + ka + c * 8;
            asm volatile("cp.async.cg.shared.global [%0], [%1], 16;" :: "r"(sbase + soff), "l"(gp));
        }
#pragma unroll
        for (int h = 0; h < 2; h++) {
            int r = row + h * 64;
            uint32_t soff = (uint32_t)(s * 16384 + 8192 + r * 64 + ((c ^ ((r >> 1) & 3)) * 16));
            const void* gp = B_ + (size_t)(n0 + r) * K + ka + c * 8;
            asm volatile("cp.async.cg.shared.global [%0], [%1], 16;" :: "r"(sbase + soff), "l"(gp));
        }
        asm volatile("cp.async.commit_group;");
    };

    stage_issue(0, 0);
    if (nch > 1) stage_issue(1, 1);

    for (int g = 0; g < nch; g++) {
        if (g == nch - 1) asm volatile("cp.async.wait_group 0;" ::: "memory");
        else              asm volatile("cp.async.wait_group 1;" ::: "memory");
        __syncthreads();
        if (g + 2 < nch) stage_issue(g + 2, (g + 2) % 3);

        const int s = g % 3;
        const uint32_t sA = sbase + s * 16384;
        const uint32_t sB = sA + 8192;
#pragma unroll
        for (int ks = 0; ks < 2; ks++) {
            uint32_t a[2][4], b[4][4];
#pragma unroll
            for (int mi = 0; mi < 2; mi++) {
                int r = warp_m + mi * 16 + (lane & 15);
                int ch = ks * 2 + (lane >> 4);
                ldsm_x4(a[mi], sA + r * 64 + ((ch ^ ((r >> 1) & 3)) * 16));
            }
#pragma unroll
            for (int nj = 0; nj < 4; nj++) {
                int r = warp_n + nj * 16 + ((lane >> 4) & 1) * 8 + (lane & 7);
                int ch = ks * 2 + ((lane >> 3) & 1);
                ldsm_x4(b[nj], sB + r * 64 + ((ch ^ ((r >> 1) & 3)) * 16));
            }
#pragma unroll
            for (int mi = 0; mi < 2; mi++)
#pragma unroll
                for (int nj = 0; nj < 4; nj++) {
                    mma16816(acc[mi][nj * 2 + 0], a[mi], b[nj][0], b[nj][1]);
                    mma16816(acc[mi][nj * 2 + 1], a[mi], b[nj][2], b[nj][3]);
                }
        }
    }

    // epilogue (measured-correct in R11): col sums + max/min over 8-row groups
    const int col0base = n0 + warp_n;
    const int gbase = (m0 + warp_m) >> 3;
#pragma unroll
    for (int ni = 0; ni < 8; ni++) {
        int col0 = col0base + ni * 8 + 2 * (lane & 3);
        float s0 = 0.f, s1 = 0.f, p0 = 0.f, p1 = 0.f;
#pragma unroll
        for (int mi = 0; mi < 2; mi++)
#pragma unroll
            for (int h = 0; h < 2; h++) {
                float z0 = acc[mi][ni][2 * h], z1 = acc[mi][ni][2 * h + 1];
                s0 += z0; p0 += z0 * z0; s1 += z1; p1 += z1 * z1;
            }
#pragma unroll
        for (int o = 4; o < 32; o <<= 1) {
            s0 += __shfl_xor_sync(0xffffffffu, s0, o);
            s1 += __shfl_xor_sync(0xffffffffu, s1, o);
            p0 += __shfl_xor_sync(0xffffffffu, p0, o);
            p1 += __shfl_xor_sync(0xffffffffu, p1, o);
        }
        if (lane < 4) {
            atomicAdd(&ps[col0], s0);  atomicAdd(&ps[col0 + 1], s1);
            atomicAdd(&ps2[col0], p0); atomicAdd(&ps2[col0 + 1], p1);
        }
#pragma unroll
        for (int mi = 0; mi < 2; mi++)
#pragma unroll
            for (int h = 0; h < 2; h++) {
                float mx0 = acc[mi][ni][2 * h], mx1 = acc[mi][ni][2 * h + 1];
                float mn0 = mx0, mn1 = mx1;
#pragma unroll
                for (int o = 4; o < 32; o <<= 1) {
                    mx0 = fmaxf(mx0, __shfl_xor_sync(0xffffffffu, mx0, o));
                    mx1 = fmaxf(mx1, __shfl_xor_sync(0xffffffffu, mx1, o));
                    mn0 = fminf(mn0, __shfl_xor_sync(0xffffffffu, mn0, o));
                    mn1 = fminf(mn1, __shfl_xor_sync(0xffffffffu, mn1, o));
                }
                if (lane < 4) {
                    int pt = gbase + 2 * mi + h;
                    *(float2*)&maxZ[(size_t)pt * Ncol + col0] = make_float2(mx0, mx1);
                    *(float2*)&minZ[(size_t)pt * Ncol + col0] = make_float2(mn0, mn1);
                }
            }
    }
}

// ======================= fp32 SGEMM (small layers only) ======================
__global__ void sgemm_nt(const float* __restrict__ A, int lda,
                         const float* __restrict__ Bw, int ldb,
                         float* __restrict__ C, int M, int K, int Ncol) {
    __shared__ float As[8][128];
    __shared__ float Bs[8][128];
    const int tid = threadIdx.x;
    const int m0 = blockIdx.y * 128;
    const int n0 = blockIdx.x * 128;
    const int tx = tid % 16;
    const int ty = tid / 16;
    float acc[8][8];
#pragma unroll
    for (int i = 0; i < 8; i++)
#pragma unroll
        for (int j = 0; j < 8; j++) acc[i][j] = 0.f;
    const int lm = tid >> 1;
    const int lk = (tid & 1) * 4;
    for (int k0 = 0; k0 < K; k0 += 8) {
#pragma unroll
        for (int i = 0; i < 4; i++) {
            int kk = lk + i;
            int gm = m0 + lm, gk = k0 + kk;
            float v = 0.f;
            if (gm < M && gk < K) v = A[(long)gm * lda + gk];
            As[kk][lm] = v;
        }
#pragma unroll
        for (int i = 0; i < 4; i++) {
            int kk = lk + i;
            int gn = n0 + lm, gk = k0 + kk;
            float v = 0.f;
            if (gn < Ncol && gk < K) v = Bw[(long)gn * ldb + gk];
            Bs[kk][lm] = v;
        }
        __syncthreads();
#pragma unroll
        for (int kk = 0; kk < 8; kk++) {
            float a[8], b[8];
#pragma unroll
            for (int i = 0; i < 8; i++) a[i] = As[kk][ty * 8 + i];
#pragma unroll
            for (int j = 0; j < 8; j++) b[j] = Bs[kk][tx * 8 + j];
#pragma unroll
            for (int i = 0; i < 8; i++)
#pragma unroll
                for (int j = 0; j < 8; j++) acc[i][j] += a[i] * b[j];
        }
        __syncthreads();
    }
#pragma unroll
    for (int i = 0; i < 8; i++) {
        int gm = m0 + ty * 8 + i;
        if (gm >= M) continue;
#pragma unroll
        for (int j = 0; j < 8; j++) {
            int gn = n0 + tx * 8 + j;
            if (gn < Ncol) C[(long)gm * Ncol + gn] = acc[i][j];
        }
    }
}

// ======================= BN pieces ===========================================
__global__ void zero2(float* a, float* b, int n) {
    int i = blockIdx.x * blockDim.x + threadIdx.x;
    if (i < n) { a[i] = 0.f; b[i] = 0.f; }
}

__global__ void bn_stats_partial(const float* __restrict__ X, int M, int C,
                                 float* __restrict__ psum, float* __restrict__ psum2) {
    int c = blockIdx.x * 32 + threadIdx.x;
    int rows_per = (M + gridDim.y - 1) / gridDim.y;
    int m0 = blockIdx.y * rows_per;
    int m1 = m0 + rows_per; if (m1 > M) m1 = M;
    float s = 0.f, s2 = 0.f;
    for (int m = m0 + threadIdx.y; m < m1; m += 8) {
        float v = X[(long)m * C + c];
        s += v; s2 += v * v;
    }
    __shared__ float sh[8][32], sh2[8][32];
    sh[threadIdx.y][threadIdx.x] = s;
    sh2[threadIdx.y][threadIdx.x] = s2;
    __syncthreads();
    if (threadIdx.y == 0) {
#pragma unroll
        for (int r = 1; r < 8; r++) { s += sh[r][threadIdx.x]; s2 += sh2[r][threadIdx.x]; }
        atomicAdd(&psum[c], s);
        atomicAdd(&psum2[c], s2);
    }
}

// stats over virtual Y[r] = U[idx[r]] + V[r>>3]  (raw, pre-BN)
__global__ void stats_gather(const float* __restrict__ U, const float* __restrict__ V,
                             const int* __restrict__ idxN, int C,
                             float* __restrict__ psum, float* __restrict__ psum2) {
    int c = blockIdx.x * 32 + threadIdx.x;
    int r0 = blockIdx.y * (MBIG / 256);
    float s = 0.f, s2 = 0.f;
    for (int r = r0 + threadIdx.y; r < r0 + (MBIG / 256); r += 8) {
        int j = idxN[r];
        float u = U[((size_t)((r >> 13) << 10) + j) * C + c];
        float v = V[(size_t)(r >> 3) * C + c];
        float y = u + v;
        s += y; s2 += y * y;
    }
    __shared__ float sh[8][32], sh2[8][32];
    sh[threadIdx.y][threadIdx.x] = s;
    sh2[threadIdx.y][threadIdx.x] = s2;
    __syncthreads();
    if (threadIdx.y == 0) {
#pragma unroll
        for (int r = 1; r < 8; r++) { s += sh[r][threadIdx.x]; s2 += sh2[r][threadIdx.x]; }
        atomicAdd(&psum[c], s);
        atomicAdd(&psum2[c], s2);
    }
}

__global__ void bn_finalize(int M, int C,
                            const float* __restrict__ psum, const float* __restrict__ psum2,
                            const float* __restrict__ gamma, const float* __restrict__ beta,
                            float* __restrict__ scale, float* __restrict__ shift) {
    int c = blockIdx.x * blockDim.x + threadIdx.x;
    if (c >= C) return;
    float mean = psum[c] / (float)M;
    float var = psum2[c] / (float)M - mean * mean;
    float sc = gamma[c] * rsqrtf(var + 1e-5f);
    scale[c] = sc;
    shift[c] = beta[c] - mean * sc;
}

__global__ void bn_apply_relu(float* __restrict__ X, long total4, int C4,
                              const float* __restrict__ scale, const float* __restrict__ shift) {
    long i = (long)blockIdx.x * blockDim.x + threadIdx.x;
    if (i >= total4) return;
    int c4 = (int)(i % C4) * 4;
    float4 v = ((float4*)X)[i];
    v.x = fmaxf(v.x * scale[c4 + 0] + shift[c4 + 0], 0.f);
    v.y = fmaxf(v.y * scale[c4 + 1] + shift[c4 + 1], 0.f);
    v.z = fmaxf(v.z * scale[c4 + 2] + shift[c4 + 2], 0.f);
    v.w = fmaxf(v.w * scale[c4 + 3] + shift[c4 + 3], 0.f);
    ((float4*)X)[i] = v;
}

// apply BN+relu, write bf16 hi/lo splits (small layers)
__global__ void bn_apply_split(const float* __restrict__ X, long total4, int C4,
                               const float* __restrict__ scale, const float* __restrict__ shift,
                               __nv_bfloat16* __restrict__ H, __nv_bfloat16* __restrict__ L) {
    long i = (long)blockIdx.x * blockDim.x + threadIdx.x;
    if (i >= total4) return;
    int c4 = (int)(i % C4) * 4;
    float4 v = ((const float4*)X)[i];
    float y0 = fmaxf(v.x * scale[c4 + 0] + shift[c4 + 0], 0.f);
    float y1 = fmaxf(v.y * scale[c4 + 1] + shift[c4 + 1], 0.f);
    float y2 = fmaxf(v.z * scale[c4 + 2] + shift[c4 + 2], 0.f);
    float y3 = fmaxf(v.w * scale[c4 + 3] + shift[c4 + 3], 0.f);
    __nv_bfloat16 h0, l0, h1, l1, h2, l2, h3, l3;
    split1(y0, h0, l0); split1(y1, h1, l1); split1(y2, h2, l2); split1(y3, h3, l3);
    __nv_bfloat162* H2 = (__nv_bfloat162*)H;
    __nv_bfloat162* L2 = (__nv_bfloat162*)L;
    H2[2 * i] = __nv_bfloat162(h0, h1); H2[2 * i + 1] = __nv_bfloat162(h2, h3);
    L2[2 * i] = __nv_bfloat162(l0, l1); L2[2 * i + 1] = __nv_bfloat162(l2, l3);
}

// ONE pass: aH/aL[r,:] = split(relu(BN1(U[idx[r]] + V[r>>3])))  (65536 rows)
__global__ void gather_split(const float* __restrict__ U, const float* __restrict__ V,
                             const int* __restrict__ idxN, int C,
                             const float* __restrict__ scale, const float* __restrict__ shift,
                             __nv_bfloat16* __restrict__ H, __nv_bfloat16* __restrict__ L) {
    int C4 = C >> 2;
    long total = (long)MBIG * C4;
    long i = (long)blockIdx.x * blockDim.x + threadIdx.x;
    if (i >= total) return;
    int c4 = (int)(i % C4);
    long r = i / C4;
    long bn = r >> 3;
    int b = (int)(bn >> 10);
    int j = idxN[r];
    float4 u = ((const float4*)U)[((size_t)((b << 10) + j)) * C4 + c4];
    float4 v = ((const float4*)V)[bn * C4 + c4];
    int c = c4 * 4;
    float y0 = fmaxf(fmaf(u.x + v.x, scale[c + 0], shift[c + 0]), 0.f);
    float y1 = fmaxf(fmaf(u.y + v.y, scale[c + 1], shift[c + 1]), 0.f);
    float y2 = fmaxf(fmaf(u.z + v.z, scale[c + 2], shift[c + 2]), 0.f);
    float y3 = fmaxf(fmaf(u.w + v.w, scale[c + 3], shift[c + 3]), 0.f);
    __nv_bfloat16 h0, l0, h1, l1, h2, l2, h3, l3;
    split1(y0, h0, l0); split1(y1, h1, l1); split1(y2, h2, l2); split1(y3, h3, l3);
    __nv_bfloat162* H2 = (__nv_bfloat162*)H;
    __nv_bfloat162* L2 = (__nv_bfloat162*)L;
    H2[2 * i] = __nv_bfloat162(h0, h1); H2[2 * i + 1] = __nv_bfloat162(h2, h3);
    L2[2 * i] = __nv_bfloat162(l0, l1); L2[2 * i + 1] = __nv_bfloat162(l2, l3);
}

// out = relu(affine(max/min)) -> bf16 splits (local_op A output, 8192 rows)
__global__ void bn_pick_split(const float* __restrict__ maxZ, const float* __restrict__ minZ, int C,
                              const float* __restrict__ scale, const float* __restrict__ shift,
                              __nv_bfloat16* __restrict__ H, __nv_bfloat16* __restrict__ L) {
    long total = (long)MPTS * C;
    long i = (long)blockIdx.x * blockDim.x + threadIdx.x;
    if (i >= total) return;
    int c = (int)(i % C);
    float s = scale[c];
    float z = (s >= 0.f) ? maxZ[i] : minZ[i];
    float y = fmaxf(fmaf(z, s, shift[c]), 0.f);
    __nv_bfloat16 h, l; split1(y, h, l);
    H[i] = h; L[i] = l;
}

// final: relu(affine(max/min)) + transpose -> out (B, C, N)
__global__ void bn_pick_tr(const float* __restrict__ maxZ, const float* __restrict__ minZ,
                           float* __restrict__ out, int C,
                           const float* __restrict__ scale, const float* __restrict__ shift) {
    __shared__ float t[32][33];
    int c = blockIdx.x * 32 + threadIdx.x;
    int n = blockIdx.y * 32 + threadIdx.y;
    int b = blockIdx.z;
    size_t i = (size_t)(b * NN + n) * C + c;
    float s = scale[c];
    float z = (s >= 0.f) ? maxZ[i] : minZ[i];
    t[threadIdx.y][threadIdx.x] = fmaxf(fmaf(z, s, shift[c]), 0.f);
    __syncthreads();
    out[((size_t)b * C + blockIdx.x * 32 + threadIdx.y) * NN + blockIdx.y * 32 + threadIdx.x] =
        t[threadIdx.x][threadIdx.y];
}

// ======================= weight splits =======================================
__global__ void wsplit(const float* __restrict__ W, int rows, int cols, int ld, int coloff,
                       __nv_bfloat16* __restrict__ H, __nv_bfloat16* __restrict__ L) {
    long total = (long)rows * cols;
    long i = (long)blockIdx.x * blockDim.x + threadIdx.x;
    if (i >= total) return;
    int r = (int)(i / cols), c = (int)(i % cols);
    float x = W[(long)r * ld + coloff + c];
    __nv_bfloat16 h, l; split1(x, h, l);
    H[i] = h; L[i] = l;
}

__global__ void wdiff_split(const float* __restrict__ W, int O, int Ck,
                            __nv_bfloat16* __restrict__ H, __nv_bfloat16* __restrict__ L) {
    long total = (long)O * Ck;
    long i = (long)blockIdx.x * blockDim.x + threadIdx.x;
    if (i >= total) return;
    int o = (int)(i / Ck), d = (int)(i % Ck);
    float x = W[(long)o * 2 * Ck + Ck + d] - W[(long)o * 2 * Ck + d];
    __nv_bfloat16 h, l; split1(x, h, l);
    H[i] = h; L[i] = l;
}

// ======================= kNN (k=8 incl. self) ================================
__global__ void knn_kernel(const float* __restrict__ xyz, int* __restrict__ idx) {
    int b = blockIdx.x;
    __shared__ float sx[NN], sy[NN], sz[NN];
    const float* base = xyz + (long)b * NN * 3;
    for (int i = threadIdx.x; i < NN; i += blockDim.x) {
        sx[i] = base[i * 3 + 0];
        sy[i] = base[i * 3 + 1];
        sz[i] = base[i * 3 + 2];
    }
    __syncthreads();
    int q = blockIdx.y * 256 + threadIdx.x;
    float qx = sx[q], qy = sy[q], qz = sz[q];
    float bd[KNN]; int bi[KNN];
#pragma unroll
    for (int t = 0; t < KNN; t++) { bd[t] = 3.0e38f; bi[t] = 0; }
    for (int jj = 0; jj < NN; jj++) {
        float dx = sx[jj] - qx, dy = sy[jj] - qy, dz = sz[jj] - qz;
        float d = dx * dx + dy * dy + dz * dz;
        if (d < bd[KNN - 1]) {
            int p = KNN - 1;
#pragma unroll
            for (int t = 0; t < KNN - 1; t++) {
                if (p > 0 && d < bd[p - 1]) { bd[p] = bd[p - 1]; bi[p] = bi[p - 1]; p--; }
            }
            bd[p] = d; bi[p] = jj;
        }
    }
#pragma unroll
    for (int t = 0; t < KNN; t++) idx[(b * NN + q) * KNN + t] = bi[t];
}

// ======================= host orchestration ==================================
extern "C" void kernel_launch(void* const* d_in, const int* in_sizes, int n_in,
                              void* d_out, int out_size) {
    const float* xyz = (const float*)d_in[0];
    const float* W1  = (const float*)d_in[1];
    const float* g1  = (const float*)d_in[2];
    const float* b1  = (const float*)d_in[3];
    const float* W2  = (const float*)d_in[4];
    const float* g2  = (const float*)d_in[5];
    const float* b2  = (const float*)d_in[6];
    const float* WA1 = (const float*)d_in[7];
    const float* gA1 = (const float*)d_in[8];
    const float* bA1 = (const float*)d_in[9];
    const float* WA2 = (const float*)d_in[10];
    const float* gA2 = (const float*)d_in[11];
    const float* bA2 = (const float*)d_in[12];
    const float* WB1 = (const float*)d_in[13];
    const float* gB1 = (const float*)d_in[14];
    const float* bB1 = (const float*)d_in[15];
    const float* WB2 = (const float*)d_in[16];
    const float* gB2 = (const float*)d_in[17];
    const float* bB2 = (const float*)d_in[18];
    float* out = (float*)d_out;

    float *U, *V, *Y, *Z, *scale, *shift, *ps, *ps2;
    __nv_bfloat16 *aH, *aL, *wH, *wL;
    int* idx;
    cudaGetSymbolAddress((void**)&U, g_U);
    cudaGetSymbolAddress((void**)&V, g_V);
    cudaGetSymbolAddress((void**)&Y, g_Y);
    cudaGetSymbolAddress((void**)&Z, g_Z);
    cudaGetSymbolAddress((void**)&aH, g_aH);
    cudaGetSymbolAddress((void**)&aL, g_aL);
    cudaGetSymbolAddress((void**)&wH, g_wH);
    cudaGetSymbolAddress((void**)&wL, g_wL);
    cudaGetSymbolAddress((void**)&idx, g_idx);
    cudaGetSymbolAddress((void**)&scale, g_scale);
    cudaGetSymbolAddress((void**)&shift, g_shift);
    cudaGetSymbolAddress((void**)&ps, g_ps);
    cudaGetSymbolAddress((void**)&ps2, g_ps2);

    auto gemm32 = [&](const float* A, int lda, const float* Bw, int ldb,
                      float* Cm, int M, int K, int Nc) {
        dim3 gs((Nc + 127) / 128, (M + 127) / 128);
        sgemm_nt<<<gs, 256>>>(A, lda, Bw, ldb, Cm, M, K, Nc);
    };
    auto gemmtc = [&](const __nv_bfloat16* Ahh, const __nv_bfloat16* All,
                      const __nv_bfloat16* Bhh, const __nv_bfloat16* Bll,
                      float* Cm, int M, int K, int Nc) {
        dim3 gs(Nc / 128, M / 128);
        gemm_mma<<<gs, 256>>>(Ahh, All, Bhh, Bll, Cm, M, K, Nc);
    };
    auto stats = [&](const float* X, int M, int C, const float* gm, const float* bt) {
        zero2<<<(C + 255) / 256, 256>>>(ps, ps2, C);
        dim3 bs(32, 8), gs(C / 32, 32);
        bn_stats_partial<<<gs, bs>>>(X, M, C, ps, ps2);
        bn_finalize<<<(C + 255) / 256, 256>>>(M, C, ps, ps2, gm, bt, scale, shift);
    };

    // Layer 1: (8192,3)@W1^T -> Y(:,64); BN+relu fp32 in place
    gemm32(xyz, 3, W1, 3, Y, MPTS, 3, 64);
    stats(Y, MPTS, 64, g1, b1);
    {
        long t4 = (long)MPTS * 64 / 4;
        bn_apply_relu<<<(unsigned)((t4 + 255) / 256), 256>>>(Y, t4, 16, scale, shift);
    }
    // Layer 2: h1@W2^T -> Z(:,256); BN+relu -> bf16 splits (h2 feat)
    gemm32(Y, 64, W2, 64, Z, MPTS, 64, 256);
    stats(Z, MPTS, 256, g2, b2);
    {
        long t4 = (long)MPTS * 256 / 4;
        bn_apply_split<<<(unsigned)((t4 + 255) / 256), 256>>>(Z, t4, 64, scale, shift, aH, aL);
    }

    // kNN indices
    {
        dim3 gs(BB, 4);
        knn_kernel<<<gs, 256>>>(xyz, idx);
    }

    auto local_op = [&](int Cin, int C2, const float* Wm1, const float* gm1, const float* bt1,
                        const float* Wm2, const float* gm2, const float* bt2, bool last) {
        // U = feat@Wd^T ; V = feat@(Wc-Wd)^T   (feat = aH/aL splits, 8192 x Cin)
        wsplit<<<((long)C2 * Cin + 255) / 256, 256>>>(Wm1, C2, Cin, 2 * Cin, 0, wH, wL);
        gemmtc(aH, aL, wH, wL, U, MPTS, Cin, C2);
        wdiff_split<<<((long)C2 * Cin + 255) / 256, 256>>>(Wm1, C2, Cin, wH, wL);
        gemmtc(aH, aL, wH, wL, V, MPTS, Cin, C2);
        // BN1 stats over virtual Y (reads U,V via L2)
        zero2<<<(C2 + 255) / 256, 256>>>(ps, ps2, C2);
        {
            dim3 bs(32, 8), gs(C2 / 32, 256);
            stats_gather<<<gs, bs>>>(U, V, idx, C2, ps, ps2);
        }
        bn_finalize<<<(C2 + 255) / 256, 256>>>(MBIG, C2, ps, ps2, gm1, bt1, scale, shift);
        // ONE pass: materialize bf16 split A for GEMM2 (BN1+relu applied inline)
        {
            long t = (long)MBIG * C2 / 4;
            gather_split<<<(unsigned)((t + 255) / 256), 256>>>(U, V, idx, C2, scale, shift, aH, aL);
        }
        // GEMM2 (M=65536), R5 mainloop + pooled epilogue (no Z materialization)
        wsplit<<<((long)C2 * C2 + 255) / 256, 256>>>(Wm2, C2, C2, C2, 0, wH, wL);
        zero2<<<(C2 + 255) / 256, 256>>>(ps, ps2, C2);
        {
            dim3 gs(C2 / 128, MBIG / 128);
            gemm_pool<<<gs, 256>>>(aH, aL, wH, wL, Y, Z, ps, ps2, C2, C2);
        }
        bn_finalize<<<(C2 + 255) / 256, 256>>>(MBIG, C2, ps, ps2, gm2, bt2, scale, shift);
        if (!last) {
            long t = (long)MPTS * C2;
            bn_pick_split<<<(unsigned)((t + 255) / 256), 256>>>(Y, Z, C2, scale, shift, aH, aL);
        } else {
            dim3 bs(32, 32), gs(C2 / 32, NN / 32, BB);
            bn_pick_tr<<<gs, bs>>>(Y, Z, out, C2, scale, shift);
        }
    };

    local_op(256, 512, WA1, gA1, bA1, WA2, gA2, bA2, false);
    local_op(512, 1024, WB1, gB1, bB1, WB2, gB2, bB2, true);
}

// round 16
// speedup vs baseline: 1.2210x; 1.0803x over previous
#include <cuda_runtime.h>
#include <cuda_bf16.h>
#include <cstdint>

#define BB 8
#define NN 1024
#define KNN 8
#define MPTS (BB * NN)        // 8192 points
#define MBIG (MPTS * KNN)     // 65536 grouped rows

// ---------------- scratch (static device globals) ---------------------------
__device__ float g_U[MPTS * 1024];
__device__ float g_V[MPTS * 1024];
__device__ float g_Y[MPTS * 1024];     // maxZ
__device__ float g_Z[MPTS * 1024];     // minZ
__device__ __nv_bfloat16 g_aH[(size_t)MBIG * 1024];
__device__ __nv_bfloat16 g_aL[(size_t)MBIG * 1024];
__device__ __nv_bfloat16 g_wH[1024 * 1024];
__device__ __nv_bfloat16 g_wL[1024 * 1024];
__device__ int   g_idx[MBIG];
__device__ float g_scale[1024];
__device__ float g_shift[1024];
__device__ float g_ps[1024];
__device__ float g_ps2[1024];

// ======================= helpers =============================================
__device__ __forceinline__ uint32_t smem_u32(const void* p) {
    uint32_t a;
    asm("{ .reg .u64 t; cvta.to.shared.u64 t, %1; cvt.u32.u64 %0, t; }" : "=r"(a) : "l"(p));
    return a;
}
__device__ __forceinline__ void ldsm_x4(uint32_t* r, uint32_t addr) {
    asm volatile("ldmatrix.sync.aligned.m8n8.x4.shared.b16 {%0,%1,%2,%3}, [%4];"
                 : "=r"(r[0]), "=r"(r[1]), "=r"(r[2]), "=r"(r[3]) : "r"(addr));
}
__device__ __forceinline__ void mma16816(float* d, const uint32_t* a, uint32_t b0, uint32_t b1) {
    asm volatile(
        "mma.sync.aligned.m16n8k16.row.col.f32.bf16.bf16.f32 "
        "{%0,%1,%2,%3}, {%4,%5,%6,%7}, {%8,%9}, {%0,%1,%2,%3};"
        : "+f"(d[0]), "+f"(d[1]), "+f"(d[2]), "+f"(d[3])
        : "r"(a[0]), "r"(a[1]), "r"(a[2]), "r"(a[3]), "r"(b0), "r"(b1));
}
__device__ __forceinline__ void split1(float y, __nv_bfloat16& h, __nv_bfloat16& l) {
    h = __float2bfloat16(y);
    l = __float2bfloat16(y - __bfloat162float(h));
}

// ============ chunk-major bf16x3 mainloop (shared by both GEMMs) =============
// Per 32-k chunk: load Ah|Al|Bh|Bl tiles ONCE, run 3 split-products
// (AhBh + AlBh + AhBl). 2 stages x 32KB = 64KB static smem (2 CTA/SM).
#define STG_BYTES 32768

#define GEMM_PROLOGUE_VARS \
    const int tid = threadIdx.x; \
    const int wid = tid >> 5, lane = tid & 31; \
    const int m0 = blockIdx.y * 128, n0 = blockIdx.x * 128; \
    const int warp_m = (wid & 3) * 32; \
    const int warp_n = (wid >> 2) * 64; \
    const uint32_t sbase = smem_u32(smem); \
    float acc[2][8][4]; \
    _Pragma("unroll") for (int i = 0; i < 2; i++) \
    _Pragma("unroll") for (int j = 0; j < 8; j++) \
    _Pragma("unroll") for (int q = 0; q < 4; q++) acc[i][j][q] = 0.f;

__device__ __forceinline__ void cm_stage_issue(
    uint32_t sbase, int s, int g, int tid, int m0, int n0, int K,
    const __nv_bfloat16* Ah, const __nv_bfloat16* Al,
    const __nv_bfloat16* Bh, const __nv_bfloat16* Bl)
{
    int ka = g * 32;
    int row = tid >> 2;
    int c = tid & 3;
#pragma unroll
    for (int h = 0; h < 2; h++) {
        int r = row + h * 64;
        uint32_t off = (uint32_t)(r * 64 + ((c ^ ((r >> 1) & 3)) * 16));
        uint32_t sa = sbase + s * STG_BYTES + off;
        const void* pa_h = Ah + (size_t)(m0 + r) * K + ka + c * 8;
        const void* pa_l = Al + (size_t)(m0 + r) * K + ka + c * 8;
        asm volatile("cp.async.cg.shared.global [%0], [%1], 16;" :: "r"(sa), "l"(pa_h));
        asm volatile("cp.async.cg.shared.global [%0], [%1], 16;" :: "r"(sa + 8192), "l"(pa_l));
        uint32_t sb = sbase + s * STG_BYTES + 16384 + off;
        const void* pb_h = Bh + (size_t)(n0 + r) * K + ka + c * 8;
        const void* pb_l = Bl + (size_t)(n0 + r) * K + ka + c * 8;
        asm volatile("cp.async.cg.shared.global [%0], [%1], 16;" :: "r"(sb), "l"(pb_h));
        asm volatile("cp.async.cg.shared.global [%0], [%1], 16;" :: "r"(sb + 8192), "l"(pb_l));
    }
    asm volatile("cp.async.commit_group;");
}

__device__ __forceinline__ void cm_mma_chunk(
    uint32_t sbase, int s, int lane, int warp_m, int warp_n, float acc[2][8][4])
{
    uint32_t base = sbase + s * STG_BYTES;
#pragma unroll
    for (int ks = 0; ks < 2; ks++) {
        uint32_t ah[2][4], al[2][4], b[4][4];
        uint32_t boff[4];
#pragma unroll
        for (int mi = 0; mi < 2; mi++) {
            int r = warp_m + mi * 16 + (lane & 15);
            int ch = ks * 2 + (lane >> 4);
            uint32_t off = r * 64 + ((ch ^ ((r >> 1) & 3)) * 16);
            ldsm_x4(ah[mi], base + off);
            ldsm_x4(al[mi], base + 8192 + off);
        }
#pragma unroll
        for (int nj = 0; nj < 4; nj++) {
            int r = warp_n + nj * 16 + ((lane >> 4) & 1) * 8 + (lane & 7);
            int ch = ks * 2 + ((lane >> 3) & 1);
            boff[nj] = r * 64 + ((ch ^ ((r >> 1) & 3)) * 16);
            ldsm_x4(b[nj], base + 16384 + boff[nj]);
        }
        // AhBh + AlBh
#pragma unroll
        for (int mi = 0; mi < 2; mi++)
#pragma unroll
            for (int nj = 0; nj < 4; nj++) {
                mma16816(acc[mi][nj * 2 + 0], ah[mi], b[nj][0], b[nj][1]);
                mma16816(acc[mi][nj * 2 + 1], ah[mi], b[nj][2], b[nj][3]);
                mma16816(acc[mi][nj * 2 + 0], al[mi], b[nj][0], b[nj][1]);
                mma16816(acc[mi][nj * 2 + 1], al[mi], b[nj][2], b[nj][3]);
            }
        // Bl reuses b registers
#pragma unroll
        for (int nj = 0; nj < 4; nj++) ldsm_x4(b[nj], base + 24576 + boff[nj]);
        // AhBl
#pragma unroll
        for (int mi = 0; mi < 2; mi++)
#pragma unroll
            for (int nj = 0; nj < 4; nj++) {
                mma16816(acc[mi][nj * 2 + 0], ah[mi], b[nj][0], b[nj][1]);
                mma16816(acc[mi][nj * 2 + 1], ah[mi], b[nj][2], b[nj][3]);
            }
    }
}

#define GEMM_MAINLOOP(K) \
    const int nk = (K) >> 5; \
    cm_stage_issue(sbase, 0, 0, tid, m0, n0, (K), Ah, Al, Bh, Bl); \
    if (nk > 1) cm_stage_issue(sbase, 1, 1, tid, m0, n0, (K), Ah, Al, Bh, Bl); \
    for (int g = 0; g < nk; g++) { \
        if (g == nk - 1) asm volatile("cp.async.wait_group 0;" ::: "memory"); \
        else             asm volatile("cp.async.wait_group 1;" ::: "memory"); \
        __syncthreads(); \
        cm_mma_chunk(sbase, g & 1, lane, warp_m, warp_n, acc); \
        if (g + 2 < nk) { \
            __syncthreads(); \
            cm_stage_issue(sbase, g & 1, g + 2, tid, m0, n0, (K), Ah, Al, Bh, Bl); \
        } \
    }

// ======================= GEMM writing C (UV layers, M=8192) ==================
__global__ void __launch_bounds__(256, 2) gemm_mma(
    const __nv_bfloat16* __restrict__ Ah, const __nv_bfloat16* __restrict__ Al,
    const __nv_bfloat16* __restrict__ Bh, const __nv_bfloat16* __restrict__ Bl,
    float* __restrict__ C, int M, int K, int Ncol)
{
    __shared__ __align__(16) unsigned char smem[2 * STG_BYTES];
    GEMM_PROLOGUE_VARS
    GEMM_MAINLOOP(K)

#pragma unroll
    for (int mi = 0; mi < 2; mi++) {
        int rbase = m0 + warp_m + mi * 16 + (lane >> 2);
#pragma unroll
        for (int ni = 0; ni < 8; ni++) {
            int col = n0 + warp_n + ni * 8 + 2 * (lane & 3);
            *(float2*)&C[(size_t)rbase * Ncol + col] = make_float2(acc[mi][ni][0], acc[mi][ni][1]);
            *(float2*)&C[(size_t)(rbase + 8) * Ncol + col] = make_float2(acc[mi][ni][2], acc[mi][ni][3]);
        }
    }
}

// ========== GEMM with pooled epilogue (M=MBIG): stats + k-max/min ============
__global__ void __launch_bounds__(256, 2) gemm_pool(
    const __nv_bfloat16* __restrict__ Ah, const __nv_bfloat16* __restrict__ Al,
    const __nv_bfloat16* __restrict__ Bh, const __nv_bfloat16* __restrict__ Bl,
    float* __restrict__ maxZ, float* __restrict__ minZ,
    float* __restrict__ ps, float* __restrict__ ps2,
    int K, int Ncol)
{
    __shared__ __align__(16) unsigned char smem[2 * STG_BYTES];
    GEMM_PROLOGUE_VARS
    GEMM_MAINLOOP(K)

    // epilogue (measured-correct in R11/R13): col sums + max/min over 8-row groups
    const int col0base = n0 + warp_n;
    const int gbase = (m0 + warp_m) >> 3;
#pragma unroll
    for (int ni = 0; ni < 8; ni++) {
        int col0 = col0base + ni * 8 + 2 * (lane & 3);
        float s0 = 0.f, s1 = 0.f, p0 = 0.f, p1 = 0.f;
#pragma unroll
        for (int mi = 0; mi < 2; mi++)
#pragma unroll
            for (int h = 0; h < 2; h++) {
                float z0 = acc[mi][ni][2 * h], z1 = acc[mi][ni][2 * h + 1];
                s0 += z0; p0 += z0 * z0; s1 += z1; p1 += z1 * z1;
            }
#pragma unroll
        for (int o = 4; o < 32; o <<= 1) {
            s0 += __shfl_xor_sync(0xffffffffu, s0, o);
            s1 += __shfl_xor_sync(0xffffffffu, s1, o);
            p0 += __shfl_xor_sync(0xffffffffu, p0, o);
            p1 += __shfl_xor_sync(0xffffffffu, p1, o);
        }
        if (lane < 4) {
            atomicAdd(&ps[col0], s0);  atomicAdd(&ps[col0 + 1], s1);
            atomicAdd(&ps2[col0], p0); atomicAdd(&ps2[col0 + 1], p1);
        }
#pragma unroll
        for (int mi = 0; mi < 2; mi++)
#pragma unroll
            for (int h = 0; h < 2; h++) {
                float mx0 = acc[mi][ni][2 * h], mx1 = acc[mi][ni][2 * h + 1];
                float mn0 = mx0, mn1 = mx1;
#pragma unroll
                for (int o = 4; o < 32; o <<= 1) {
                    mx0 = fmaxf(mx0, __shfl_xor_sync(0xffffffffu, mx0, o));
                    mx1 = fmaxf(mx1, __shfl_xor_sync(0xffffffffu, mx1, o));
                    mn0 = fminf(mn0, __shfl_xor_sync(0xffffffffu, mn0, o));
                    mn1 = fminf(mn1, __shfl_xor_sync(0xffffffffu, mn1, o));
                }
                if (lane < 4) {
                    int pt = gbase + 2 * mi + h;
                    *(float2*)&maxZ[(size_t)pt * Ncol + col0] = make_float2(mx0, mx1);
                    *(float2*)&minZ[(size_t)pt * Ncol + col0] = make_float2(mn0, mn1);
                }
            }
    }
}

// ======================= fp32 SGEMM (small layers only) ======================
__global__ void sgemm_nt(const float* __restrict__ A, int lda,
                         const float* __restrict__ Bw, int ldb,
                         float* __restrict__ C, int M, int K, int Ncol) {
    __shared__ float As[8][128];
    __shared__ float Bs[8][128];
    const int tid = threadIdx.x;
    const int m0 = blockIdx.y * 128;
    const int n0 = blockIdx.x * 128;
    const int tx = tid % 16;
    const int ty = tid / 16;
    float acc[8][8];
#pragma unroll
    for (int i = 0; i < 8; i++)
#pragma unroll
        for (int j = 0; j < 8; j++) acc[i][j] = 0.f;
    const int lm = tid >> 1;
    const int lk = (tid & 1) * 4;
    for (int k0 = 0; k0 < K; k0 += 8) {
#pragma unroll
        for (int i = 0; i < 4; i++) {
            int kk = lk + i;
            int gm = m0 + lm, gk = k0 + kk;
            float v = 0.f;
            if (gm < M && gk < K) v = A[(long)gm * lda + gk];
            As[kk][lm] = v;
        }
#pragma unroll
        for (int i = 0; i < 4; i++) {
            int kk = lk + i;
            int gn = n0 + lm, gk = k0 + kk;
            float v = 0.f;
            if (gn < Ncol && gk < K) v = Bw[(long)gn * ldb + gk];
            Bs[kk][lm] = v;
        }
        __syncthreads();
#pragma unroll
        for (int kk = 0; kk < 8; kk++) {
            float a[8], b[8];
#pragma unroll
            for (int i = 0; i < 8; i++) a[i] = As[kk][ty * 8 + i];
#pragma unroll
            for (int j = 0; j < 8; j++) b[j] = Bs[kk][tx * 8 + j];
#pragma unroll
            for (int i = 0; i < 8; i++)
#pragma unroll
                for (int j = 0; j < 8; j++) acc[i][j] += a[i] * b[j];
        }
        __syncthreads();
    }
#pragma unroll
    for (int i = 0; i < 8; i++) {
        int gm = m0 + ty * 8 + i;
        if (gm >= M) continue;
#pragma unroll
        for (int j = 0; j < 8; j++) {
            int gn = n0 + tx * 8 + j;
            if (gn < Ncol) C[(long)gm * Ncol + gn] = acc[i][j];
        }
    }
}

// ======================= BN pieces ===========================================
__global__ void zero2(float* a, float* b, int n) {
    int i = blockIdx.x * blockDim.x + threadIdx.x;
    if (i < n) { a[i] = 0.f; b[i] = 0.f; }
}

__global__ void bn_stats_partial(const float* __restrict__ X, int M, int C,
                                 float* __restrict__ psum, float* __restrict__ psum2) {
    int c = blockIdx.x * 32 + threadIdx.x;
    int rows_per = (M + gridDim.y - 1) / gridDim.y;
    int m0 = blockIdx.y * rows_per;
    int m1 = m0 + rows_per; if (m1 > M) m1 = M;
    float s = 0.f, s2 = 0.f;
    for (int m = m0 + threadIdx.y; m < m1; m += 8) {
        float v = X[(long)m * C + c];
        s += v; s2 += v * v;
    }
    __shared__ float sh[8][32], sh2[8][32];
    sh[threadIdx.y][threadIdx.x] = s;
    sh2[threadIdx.y][threadIdx.x] = s2;
    __syncthreads();
    if (threadIdx.y == 0) {
#pragma unroll
        for (int r = 1; r < 8; r++) { s += sh[r][threadIdx.x]; s2 += sh2[r][threadIdx.x]; }
        atomicAdd(&psum[c], s);
        atomicAdd(&psum2[c], s2);
    }
}

// stats over virtual Y[r] = U[idx[r]] + V[r>>3]  (raw, pre-BN)
__global__ void stats_gather(const float* __restrict__ U, const float* __restrict__ V,
                             const int* __restrict__ idxN, int C,
                             float* __restrict__ psum, float* __restrict__ psum2) {
    int c = blockIdx.x * 32 + threadIdx.x;
    int r0 = blockIdx.y * (MBIG / 256);
    float s = 0.f, s2 = 0.f;
    for (int r = r0 + threadIdx.y; r < r0 + (MBIG / 256); r += 8) {
        int j = idxN[r];
        float u = U[((size_t)((r >> 13) << 10) + j) * C + c];
        float v = V[(size_t)(r >> 3) * C + c];
        float y = u + v;
        s += y; s2 += y * y;
    }
    __shared__ float sh[8][32], sh2[8][32];
    sh[threadIdx.y][threadIdx.x] = s;
    sh2[threadIdx.y][threadIdx.x] = s2;
    __syncthreads();
    if (threadIdx.y == 0) {
#pragma unroll
        for (int r = 1; r < 8; r++) { s += sh[r][threadIdx.x]; s2 += sh2[r][threadIdx.x]; }
        atomicAdd(&psum[c], s);
        atomicAdd(&psum2[c], s2);
    }
}

__global__ void bn_finalize(int M, int C,
                            const float* __restrict__ psum, const float* __restrict__ psum2,
                            const float* __restrict__ gamma, const float* __restrict__ beta,
                            float* __restrict__ scale, float* __restrict__ shift) {
    int c = blockIdx.x * blockDim.x + threadIdx.x;
    if (c >= C) return;
    float mean = psum[c] / (float)M;
    float var = psum2[c] / (float)M - mean * mean;
    float sc = gamma[c] * rsqrtf(var + 1e-5f);
    scale[c] = sc;
    shift[c] = beta[c] - mean * sc;
}

__global__ void bn_apply_relu(float* __restrict__ X, long total4, int C4,
                              const float* __restrict__ scale, const float* __restrict__ shift) {
    long i = (long)blockIdx.x * blockDim.x + threadIdx.x;
    if (i >= total4) return;
    int c4 = (int)(i % C4) * 4;
    float4 v = ((float4*)X)[i];
    v.x = fmaxf(v.x * scale[c4 + 0] + shift[c4 + 0], 0.f);
    v.y = fmaxf(v.y * scale[c4 + 1] + shift[c4 + 1], 0.f);
    v.z = fmaxf(v.z * scale[c4 + 2] + shift[c4 + 2], 0.f);
    v.w = fmaxf(v.w * scale[c4 + 3] + shift[c4 + 3], 0.f);
    ((float4*)X)[i] = v;
}

// apply BN+relu, write bf16 hi/lo splits (small layers)
__global__ void bn_apply_split(const float* __restrict__ X, long total4, int C4,
                               const float* __restrict__ scale, const float* __restrict__ shift,
                               __nv_bfloat16* __restrict__ H, __nv_bfloat16* __restrict__ L) {
    long i = (long)blockIdx.x * blockDim.x + threadIdx.x;
    if (i >= total4) return;
    int c4 = (int)(i % C4) * 4;
    float4 v = ((const float4*)X)[i];
    float y0 = fmaxf(v.x * scale[c4 + 0] + shift[c4 + 0], 0.f);
    float y1 = fmaxf(v.y * scale[c4 + 1] + shift[c4 + 1], 0.f);
    float y2 = fmaxf(v.z * scale[c4 + 2] + shift[c4 + 2], 0.f);
    float y3 = fmaxf(v.w * scale[c4 + 3] + shift[c4 + 3], 0.f);
    __nv_bfloat16 h0, l0, h1, l1, h2, l2, h3, l3;
    split1(y0, h0, l0); split1(y1, h1, l1); split1(y2, h2, l2); split1(y3, h3, l3);
    __nv_bfloat162* H2 = (__nv_bfloat162*)H;
    __nv_bfloat162* L2 = (__nv_bfloat162*)L;
    H2[2 * i] = __nv_bfloat162(h0, h1); H2[2 * i + 1] = __nv_bfloat162(h2, h3);
    L2[2 * i] = __nv_bfloat162(l0, l1); L2[2 * i + 1] = __nv_bfloat162(l2, l3);
}

// ONE pass: aH/aL[r,:] = split(relu(BN1(U[idx[r]] + V[r>>3])))  (65536 rows)
__global__ void gather_split(const float* __restrict__ U, const float* __restrict__ V,
                             const int* __restrict__ idxN, int C,
                             const float* __restrict__ scale, const float* __restrict__ shift,
                             __nv_bfloat16* __restrict__ H, __nv_bfloat16* __restrict__ L) {
    int C4 = C >> 2;
    long total = (long)MBIG * C4;
    long i = (long)blockIdx.x * blockDim.x + threadIdx.x;
    if (i >= total) return;
    int c4 = (int)(i % C4);
    long r = i / C4;
    long bn = r >> 3;
    int b = (int)(bn >> 10);
    int j = idxN[r];
    float4 u = ((const float4*)U)[((size_t)((b << 10) + j)) * C4 + c4];
    float4 v = ((const float4*)V)[bn * C4 + c4];
    int c = c4 * 4;
    float y0 = fmaxf(fmaf(u.x + v.x, scale[c + 0], shift[c + 0]), 0.f);
    float y1 = fmaxf(fmaf(u.y + v.y, scale[c + 1], shift[c + 1]), 0.f);
    float y2 = fmaxf(fmaf(u.z + v.z, scale[c + 2], shift[c + 2]), 0.f);
    float y3 = fmaxf(fmaf(u.w + v.w, scale[c + 3], shift[c + 3]), 0.f);
    __nv_bfloat16 h0, l0, h1, l1, h2, l2, h3, l3;
    split1(y0, h0, l0); split1(y1, h1, l1); split1(y2, h2, l2); split1(y3, h3, l3);
    __nv_bfloat162* H2 = (__nv_bfloat162*)H;
    __nv_bfloat162* L2 = (__nv_bfloat162*)L;
    H2[2 * i] = __nv_bfloat162(h0, h1); H2[2 * i + 1] = __nv_bfloat162(h2, h3);
    L2[2 * i] = __nv_bfloat162(l0, l1); L2[2 * i + 1] = __nv_bfloat162(l2, l3);
}

// out = relu(affine(max/min)) -> bf16 splits (local_op A output, 8192 rows)
__global__ void bn_pick_split(const float* __restrict__ maxZ, const float* __restrict__ minZ, int C,
                              const float* __restrict__ scale, const float* __restrict__ shift,
                              __nv_bfloat16* __restrict__ H, __nv_bfloat16* __restrict__ L) {
    long total = (long)MPTS * C;
    long i = (long)blockIdx.x * blockDim.x + threadIdx.x;
    if (i >= total) return;
    int c = (int)(i % C);
    float s = scale[c];
    float z = (s >= 0.f) ? maxZ[i] : minZ[i];
    float y = fmaxf(fmaf(z, s, shift[c]), 0.f);
    __nv_bfloat16 h, l; split1(y, h, l);
    H[i] = h; L[i] = l;
}

// final: relu(affine(max/min)) + transpose -> out (B, C, N)
__global__ void bn_pick_tr(const float* __restrict__ maxZ, const float* __restrict__ minZ,
                           float* __restrict__ out, int C,
                           const float* __restrict__ scale, const float* __restrict__ shift) {
    __shared__ float t[32][33];
    int c = blockIdx.x * 32 + threadIdx.x;
    int n = blockIdx.y * 32 + threadIdx.y;
    int b = blockIdx.z;
    size_t i = (size_t)(b * NN + n) * C + c;
    float s = scale[c];
    float z = (s >= 0.f) ? maxZ[i] : minZ[i];
    t[threadIdx.y][threadIdx.x] = fmaxf(fmaf(z, s, shift[c]), 0.f);
    __syncthreads();
    out[((size_t)b * C + blockIdx.x * 32 + threadIdx.y) * NN + blockIdx.y * 32 + threadIdx.x] =
        t[threadIdx.x][threadIdx.y];
}

// ======================= weight splits =======================================
__global__ void wsplit(const float* __restrict__ W, int rows, int cols, int ld, int coloff,
                       __nv_bfloat16* __restrict__ H, __nv_bfloat16* __restrict__ L) {
    long total = (long)rows * cols;
    long i = (long)blockIdx.x * blockDim.x + threadIdx.x;
    if (i >= total) return;
    int r = (int)(i / cols), c = (int)(i % cols);
    float x = W[(long)r * ld + coloff + c];
    __nv_bfloat16 h, l; split1(x, h, l);
    H[i] = h; L[i] = l;
}

__global__ void wdiff_split(const float* __restrict__ W, int O, int Ck,
                            __nv_bfloat16* __restrict__ H, __nv_bfloat16* __restrict__ L) {
    long total = (long)O * Ck;
    long i = (long)blockIdx.x * blockDim.x + threadIdx.x;
    if (i >= total) return;
    int o = (int)(i / Ck), d = (int)(i % Ck);
    float x = W[(long)o * 2 * Ck + Ck + d] - W[(long)o * 2 * Ck + d];
    __nv_bfloat16 h, l; split1(x, h, l);
    H[i] = h; L[i] = l;
}

// ======================= kNN (k=8 incl. self) ================================
__global__ void knn_kernel(const float* __restrict__ xyz, int* __restrict__ idx) {
    int b = blockIdx.x;
    __shared__ float sx[NN], sy[NN], sz[NN];
    const float* base = xyz + (long)b * NN * 3;
    for (int i = threadIdx.x; i < NN; i += blockDim.x) {
        sx[i] = base[i * 3 + 0];
        sy[i] = base[i * 3 + 1];
        sz[i] = base[i * 3 + 2];
    }
    __syncthreads();
    int q = blockIdx.y * 256 + threadIdx.x;
    float qx = sx[q], qy = sy[q], qz = sz[q];
    float bd[KNN]; int bi[KNN];
#pragma unroll
    for (int t = 0; t < KNN; t++) { bd[t] = 3.0e38f; bi[t] = 0; }
    for (int jj = 0; jj < NN; jj++) {
        float dx = sx[jj] - qx, dy = sy[jj] - qy, dz = sz[jj] - qz;
        float d = dx * dx + dy * dy + dz * dz;
        if (d < bd[KNN - 1]) {
            int p = KNN - 1;
#pragma unroll
            for (int t = 0; t < KNN - 1; t++) {
                if (p > 0 && d < bd[p - 1]) { bd[p] = bd[p - 1]; bi[p] = bi[p - 1]; p--; }
            }
            bd[p] = d; bi[p] = jj;
        }
    }
#pragma unroll
    for (int t = 0; t < KNN; t++) idx[(b * NN + q) * KNN + t] = bi[t];
}

// ======================= host orchestration ==================================
extern "C" void kernel_launch(void* const* d_in, const int* in_sizes, int n_in,
                              void* d_out, int out_size) {
    const float* xyz = (const float*)d_in[0];
    const float* W1  = (const float*)d_in[1];
    const float* g1  = (const float*)d_in[2];
    const float* b1  = (const float*)d_in[3];
    const float* W2  = (const float*)d_in[4];
    const float* g2  = (const float*)d_in[5];
    const float* b2  = (const float*)d_in[6];
    const float* WA1 = (const float*)d_in[7];
    const float* gA1 = (const float*)d_in[8];
    const float* bA1 = (const float*)d_in[9];
    const float* WA2 = (const float*)d_in[10];
    const float* gA2 = (const float*)d_in[11];
    const float* bA2 = (const float*)d_in[12];
    const float* WB1 = (const float*)d_in[13];
    const float* gB1 = (const float*)d_in[14];
    const float* bB1 = (const float*)d_in[15];
    const float* WB2 = (const float*)d_in[16];
    const float* gB2 = (const float*)d_in[17];
    const float* bB2 = (const float*)d_in[18];
    float* out = (float*)d_out;

    float *U, *V, *Y, *Z, *scale, *shift, *ps, *ps2;
    __nv_bfloat16 *aH, *aL, *wH, *wL;
    int* idx;
    cudaGetSymbolAddress((void**)&U, g_U);
    cudaGetSymbolAddress((void**)&V, g_V);
    cudaGetSymbolAddress((void**)&Y, g_Y);
    cudaGetSymbolAddress((void**)&Z, g_Z);
    cudaGetSymbolAddress((void**)&aH, g_aH);
    cudaGetSymbolAddress((void**)&aL, g_aL);
    cudaGetSymbolAddress((void**)&wH, g_wH);
    cudaGetSymbolAddress((void**)&wL, g_wL);
    cudaGetSymbolAddress((void**)&idx, g_idx);
    cudaGetSymbolAddress((void**)&scale, g_scale);
    cudaGetSymbolAddress((void**)&shift, g_shift);
    cudaGetSymbolAddress((void**)&ps, g_ps);
    cudaGetSymbolAddress((void**)&ps2, g_ps2);

    auto gemm32 = [&](const float* A, int lda, const float* Bw, int ldb,
                      float* Cm, int M, int K, int Nc) {
        dim3 gs((Nc + 127) / 128, (M + 127) / 128);
        sgemm_nt<<<gs, 256>>>(A, lda, Bw, ldb, Cm, M, K, Nc);
    };
    auto gemmtc = [&](const __nv_bfloat16* Ahh, const __nv_bfloat16* All,
                      const __nv_bfloat16* Bhh, const __nv_bfloat16* Bll,
                      float* Cm, int M, int K, int Nc) {
        dim3 gs(Nc / 128, M / 128);
        gemm_mma<<<gs, 256>>>(Ahh, All, Bhh, Bll, Cm, M, K, Nc);
    };
    auto stats = [&](const float* X, int M, int C, const float* gm, const float* bt) {
        zero2<<<(C + 255) / 256, 256>>>(ps, ps2, C);
        dim3 bs(32, 8), gs(C / 32, 32);
        bn_stats_partial<<<gs, bs>>>(X, M, C, ps, ps2);
        bn_finalize<<<(C + 255) / 256, 256>>>(M, C, ps, ps2, gm, bt, scale, shift);
    };

    // Layer 1: (8192,3)@W1^T -> Y(:,64); BN+relu fp32 in place
    gemm32(xyz, 3, W1, 3, Y, MPTS, 3, 64);
    stats(Y, MPTS, 64, g1, b1);
    {
        long t4 = (long)MPTS * 64 / 4;
        bn_apply_relu<<<(unsigned)((t4 + 255) / 256), 256>>>(Y, t4, 16, scale, shift);
    }
    // Layer 2: h1@W2^T -> Z(:,256); BN+relu -> bf16 splits (h2 feat)
    gemm32(Y, 64, W2, 64, Z, MPTS, 64, 256);
    stats(Z, MPTS, 256, g2, b2);
    {
        long t4 = (long)MPTS * 256 / 4;
        bn_apply_split<<<(unsigned)((t4 + 255) / 256), 256>>>(Z, t4, 64, scale, shift, aH, aL);
    }

    // kNN indices
    {
        dim3 gs(BB, 4);
        knn_kernel<<<gs, 256>>>(xyz, idx);
    }

    auto local_op = [&](int Cin, int C2, const float* Wm1, const float* gm1, const float* bt1,
                        const float* Wm2, const float* gm2, const float* bt2, bool last) {
        // U = feat@Wd^T ; V = feat@(Wc-Wd)^T   (feat = aH/aL splits, 8192 x Cin)
        wsplit<<<((long)C2 * Cin + 255) / 256, 256>>>(Wm1, C2, Cin, 2 * Cin, 0, wH, wL);
        gemmtc(aH, aL, wH, wL, U, MPTS, Cin, C2);
        wdiff_split<<<((long)C2 * Cin + 255) / 256, 256>>>(Wm1, C2, Cin, wH, wL);
        gemmtc(aH, aL, wH, wL, V, MPTS, Cin, C2);
        // BN1 stats over virtual Y (reads U,V via L2)
        zero2<<<(C2 + 255) / 256, 256>>>(ps, ps2, C2);
        {
            dim3 bs(32, 8), gs(C2 / 32, 256);
            stats_gather<<<gs, bs>>>(U, V, idx, C2, ps, ps2);
        }
        bn_finalize<<<(C2 + 255) / 256, 256>>>(MBIG, C2, ps, ps2, gm1, bt1, scale, shift);
        // ONE pass: materialize bf16 split A for GEMM2 (BN1+relu applied inline)
        {
            long t = (long)MBIG * C2 / 4;
            gather_split<<<(unsigned)((t + 255) / 256), 256>>>(U, V, idx, C2, scale, shift, aH, aL);
        }
        // GEMM2 (M=65536), chunk-major mainloop + pooled epilogue
        wsplit<<<((long)C2 * C2 + 255) / 256, 256>>>(Wm2, C2, C2, C2, 0, wH, wL);
        zero2<<<(C2 + 255) / 256, 256>>>(ps, ps2, C2);
        {
            dim3 gs(C2 / 128, MBIG / 128);
            gemm_pool<<<gs, 256>>>(aH, aL, wH, wL, Y, Z, ps, ps2, C2, C2);
        }
        bn_finalize<<<(C2 + 255) / 256, 256>>>(MBIG, C2, ps, ps2, gm2, bt2, scale, shift);
        if (!last) {
            long t = (long)MPTS * C2;
            bn_pick_split<<<(unsigned)((t + 255) / 256), 256>>>(Y, Z, C2, scale, shift, aH, aL);
        } else {
            dim3 bs(32, 32), gs(C2 / 32, NN / 32, BB);
            bn_pick_tr<<<gs, bs>>>(Y, Z, out, C2, scale, shift);
        }
    };

    local_op(256, 512, WA1, gA1, bA1, WA2, gA2, bA2, false);
    local_op(512, 1024, WB1, gB1, bB1, WB2, gB2, bB2, true);
}